// round 14
// baseline (speedup 1.0000x reference)
#include <cuda_runtime.h>
#include <cuda_bf16.h>
#include <cuda_fp8.h>
#include <cstdint>
#include <math.h>

#define HH 16
#define DD 1024
#define DH 64
#define FF 2048
#define TT 2048
#define SS 512

static __constant__ float kLnEps = 1e-5f;
#define SCALE 0.125f  /* 1/sqrt(1024/16) = 1/8 */

// ---------------- scratch (device globals, no allocations) ----------------
__device__ float g_from[FF * DD];
__device__ float g_to[TT * DD];
__device__ float g_q[FF * DD];
__device__ float g_v[TT * DD];
__device__ float g_cb[TT * HH];
__device__ float g_scores[(size_t)HH * FF * TT];   // reused as bf16 probs
__device__ float g_res[FF * DD];
__device__ float g_psum[(size_t)HH * FF * 8];
__device__ float g_rinv[HH * FF];
__device__ uint8_t g_q8[(size_t)HH * FF * DD];     // e4m3 mixed-q
__device__ uint8_t g_k8[(size_t)TT * DD];          // e4m3 k
__device__ __nv_bfloat16 g_fh[(size_t)FF * DD];
__device__ __nv_bfloat16 g_th[(size_t)TT * DD];
__device__ __nv_bfloat16 g_ch[(size_t)FF * DD];    // bf16 ctx (written by ctx kernel)
__device__ __nv_bfloat16 g_wqh[(size_t)DD * DD];
__device__ __nv_bfloat16 g_wkh[(size_t)DD * DD];
__device__ __nv_bfloat16 g_wvh[(size_t)DD * DD];
__device__ __nv_bfloat16 g_wdh[(size_t)DD * DD];
__device__ __nv_bfloat16 g_vth[(size_t)DD * TT];

// mma.sync m16n8k16 bf16 (portable HMMA; tcgen05 PTX rejected by compute_103)
#define MMA16816(d, a, b0, b1)                                              \
    asm volatile(                                                           \
        "mma.sync.aligned.m16n8k16.row.col.f32.bf16.bf16.f32 "              \
        "{%0,%1,%2,%3}, {%4,%5,%6,%7}, {%8,%9}, {%0,%1,%2,%3};"             \
        : "+f"((d)[0]), "+f"((d)[1]), "+f"((d)[2]), "+f"((d)[3])            \
        : "r"((a)[0]), "r"((a)[1]), "r"((a)[2]), "r"((a)[3]),               \
          "r"(b0), "r"(b1))

// mma.sync m16n8k32 e4m3 (fp8, sm_89+)
#define MMAF8(d, a, b0, b1)                                                 \
    asm volatile(                                                           \
        "mma.sync.aligned.m16n8k32.row.col.f32.e4m3.e4m3.f32 "              \
        "{%0,%1,%2,%3}, {%4,%5,%6,%7}, {%8,%9}, {%0,%1,%2,%3};"             \
        : "+f"((d)[0]), "+f"((d)[1]), "+f"((d)[2]), "+f"((d)[3])            \
        : "r"((a)[0]), "r"((a)[1]), "r"((a)[2]), "r"((a)[3]),               \
          "r"(b0), "r"(b1))

__device__ __forceinline__ uint32_t smem_u32(const void* p) {
    uint32_t a;
    asm("{ .reg .u64 t; cvta.to.shared.u64 t, %1; cvt.u32.u64 %0, t; }" : "=r"(a) : "l"(p));
    return a;
}
__device__ __forceinline__ void cp16(uint32_t dst, const void* src) {
    asm volatile("cp.async.cg.shared.global [%0], [%1], 16;" :: "r"(dst), "l"(src));
}
#define CP_COMMIT() asm volatile("cp.async.commit_group;" ::: "memory")
#define CP_WAIT1()  asm volatile("cp.async.wait_group 1;" ::: "memory")
#define CP_WAIT0()  asm volatile("cp.async.wait_group 0;" ::: "memory")

__device__ __forceinline__ uint32_t pack_fp8x4(float a, float b, float c, float d) {
    __nv_fp8x2_storage_t lo = __nv_cvt_float2_to_fp8x2(make_float2(a, b),
                                                       __NV_SATFINITE, __NV_E4M3);
    __nv_fp8x2_storage_t hi = __nv_cvt_float2_to_fp8x2(make_float2(c, d),
                                                       __NV_SATFINITE, __NV_E4M3);
    return (uint32_t)lo | ((uint32_t)hi << 16);
}

// ---------------- gather (also emits bf16 planes) ----------------
__global__ void gather_kernel(const float* __restrict__ hidden,
                              const int* __restrict__ fpos,
                              const int* __restrict__ tpos) {
    int row = blockIdx.x;
    int fi = fpos[row] & (SS - 1);
    int ti = tpos[row] & (SS - 1);
    const float4* srcf = (const float4*)(hidden + (size_t)fi * DD);
    const float4* srct = (const float4*)(hidden + (size_t)ti * DD);
    float4* dstf = (float4*)(g_from + (size_t)row * DD);
    float4* dstt = (float4*)(g_to + (size_t)row * DD);
    for (int i = threadIdx.x; i < DD / 4; i += blockDim.x) {
        float4 f = srcf[i];
        float4 t = srct[i];
        dstf[i] = f;
        dstt[i] = t;
        size_t o = (size_t)row * DD + i * 4;
        *(__nv_bfloat162*)&g_fh[o]     = __nv_bfloat162(__float2bfloat16(f.x), __float2bfloat16(f.y));
        *(__nv_bfloat162*)&g_fh[o + 2] = __nv_bfloat162(__float2bfloat16(f.z), __float2bfloat16(f.w));
        *(__nv_bfloat162*)&g_th[o]     = __nv_bfloat162(__float2bfloat16(t.x), __float2bfloat16(t.y));
        *(__nv_bfloat162*)&g_th[o + 2] = __nv_bfloat162(__float2bfloat16(t.z), __float2bfloat16(t.w));
    }
}

// ---------------- transpose (hi only): in[R,C] fp32 -> out[C][R] bf16 ----
__global__ void transpose_h_kernel(const float* __restrict__ in, int R, int C,
                                   __nv_bfloat16* __restrict__ oh) {
    __shared__ float t[32][33];
    int bc = blockIdx.x * 32, br = blockIdx.y * 32;
    int tx = threadIdx.x, ty = threadIdx.y;   // 32 x 8
#pragma unroll
    for (int j = 0; j < 32; j += 8)
        t[ty + j][tx] = in[(size_t)(br + ty + j) * C + bc + tx];
    __syncthreads();
#pragma unroll
    for (int j = 0; j < 32; j += 8)
        oh[(size_t)(bc + ty + j) * R + br + tx] = __float2bfloat16(t[tx][ty + j]);
}

// ---------------- cb ----------------
__global__ void cb_kernel(const float* __restrict__ Wcb, float* __restrict__ cb) {
    int t = blockIdx.x;
    int lane = threadIdx.x & 31, w = threadIdx.x >> 5;
    const float* row = g_to + (size_t)t * DD;
#pragma unroll
    for (int hh = 0; hh < 2; hh++) {
        int h = w * 2 + hh;
        float s = 0.f;
        for (int d = lane; d < DD; d += 32) s += row[d] * Wcb[d * HH + h];
#pragma unroll
        for (int o = 16; o; o >>= 1) s += __shfl_down_sync(0xffffffffu, s, o);
        if (lane == 0) cb[t * HH + h] = s;
    }
}

// ---------------- split mixed-q -> e4m3 ----------------
__global__ void split_q_kernel(const float* __restrict__ q, const float* __restrict__ mixing,
                               uint8_t* __restrict__ q8) {
    int h = blockIdx.x >> 11;
    int f = blockIdx.x & (FF - 1);
    int d = threadIdx.x * 4;
    float4 x = *(const float4*)&q[(size_t)f * DD + d];
    float4 m = *(const float4*)&mixing[(size_t)h * DD + d];
    size_t o = ((size_t)h * FF + f) * DD + d;
    *(uint32_t*)&q8[o] = pack_fp8x4(x.x * m.x, x.y * m.y, x.z * m.z, x.w * m.w);
}

// ---------------- dense GEMM, single-product bf16, double-buffered -------
#define GM_STAGE 20480
#define GM_SMEM  (2 * GM_STAGE + 128 * 4)

__global__ __launch_bounds__(256) void gemm_sp_kernel(
    const __nv_bfloat16* __restrict__ Ah_,
    const __nv_bfloat16* __restrict__ Bh_,
    const float* __restrict__ bias, const float* __restrict__ addend,
    float* __restrict__ C, uint8_t* __restrict__ C8)
{
    extern __shared__ char gsm[];
    float* sbias = (float*)(gsm + 2 * GM_STAGE);
    uint32_t smb = smem_u32(gsm);

    int tid = threadIdx.x;
    int lane = tid & 31, wid = tid >> 5;
    int bm = blockIdx.y * 128, bn = blockIdx.x * 128;
    int wm = (wid & 3) * 32, wn = (wid >> 2) * 64;

    const __nv_bfloat16* Ah = Ah_ + (size_t)bm * DD;
    const __nv_bfloat16* Bh = Bh_ + (size_t)bn * DD;

    if (tid < 128) sbias[tid] = bias ? bias[bn + tid] : 0.f;

    float acc[2][8][4];
#pragma unroll
    for (int mi = 0; mi < 2; mi++)
#pragma unroll
        for (int ni = 0; ni < 8; ni++)
#pragma unroll
            for (int j = 0; j < 4; j++) acc[mi][ni][j] = 0.f;

    int frow = tid >> 1;
    int fc = (tid & 1) * 16;
    uint32_t fb = frow * 80 + (tid & 1) * 32;

    auto issue = [&](int c, int s) {
        int k0 = c * 32;
        uint32_t sb = smb + s * GM_STAGE;
        size_t go = (size_t)frow * DD + k0 + fc;
        uint32_t d = sb + fb;
        cp16(d, Ah + go);               cp16(d + 16, Ah + go + 8);
        cp16(d + 10240, Bh + go);       cp16(d + 10240 + 16, Bh + go + 8);
        CP_COMMIT();
    };

    issue(0, 0);

    for (int c = 0; c < 32; c++) {
        int s = c & 1;
        if (c < 31) issue(c + 1, s ^ 1);
        if (c < 31) { CP_WAIT1(); } else { CP_WAIT0(); }
        __syncthreads();

        const __nv_bfloat16* pAh = (const __nv_bfloat16*)(gsm + s * GM_STAGE);
        const __nv_bfloat16* pBh = pAh + 5120;

#pragma unroll
        for (int ks = 0; ks < 2; ks++) {
            int kk = ks * 16 + 2 * (lane & 3);
            uint32_t ah[2][4];
#pragma unroll
            for (int mi = 0; mi < 2; mi++) {
                int r = wm + mi * 16 + (lane >> 2);
                ah[mi][0] = *(const uint32_t*)&pAh[r * 40 + kk];
                ah[mi][1] = *(const uint32_t*)&pAh[(r + 8) * 40 + kk];
                ah[mi][2] = *(const uint32_t*)&pAh[r * 40 + kk + 8];
                ah[mi][3] = *(const uint32_t*)&pAh[(r + 8) * 40 + kk + 8];
            }
#pragma unroll
            for (int ni = 0; ni < 8; ni++) {
                int n = wn + ni * 8 + (lane >> 2);
                uint32_t bh0 = *(const uint32_t*)&pBh[n * 40 + kk];
                uint32_t bh1 = *(const uint32_t*)&pBh[n * 40 + kk + 8];
#pragma unroll
                for (int mi = 0; mi < 2; mi++)
                    MMA16816(acc[mi][ni], ah[mi], bh0, bh1);
            }
        }
        __syncthreads();
    }

    if (C8) {
        uint8_t* ob = C8 + (size_t)bm * DD + bn;
#pragma unroll
        for (int mi = 0; mi < 2; mi++) {
            int r = wm + mi * 16 + (lane >> 2);
#pragma unroll
            for (int ni = 0; ni < 8; ni++) {
                int tcol = wn + ni * 8 + 2 * (lane & 3);
                float b0 = sbias[tcol], b1 = sbias[tcol + 1];
                __nv_fp8x2_storage_t v0 = __nv_cvt_float2_to_fp8x2(
                    make_float2(acc[mi][ni][0] + b0, acc[mi][ni][1] + b1),
                    __NV_SATFINITE, __NV_E4M3);
                __nv_fp8x2_storage_t v1 = __nv_cvt_float2_to_fp8x2(
                    make_float2(acc[mi][ni][2] + b0, acc[mi][ni][3] + b1),
                    __NV_SATFINITE, __NV_E4M3);
                *(unsigned short*)&ob[(size_t)r * DD + tcol] = v0;
                *(unsigned short*)&ob[(size_t)(r + 8) * DD + tcol] = v1;
            }
        }
    } else {
        float* outp = C + (size_t)bm * DD + bn;
        const float* add = addend ? addend + (size_t)bm * DD + bn : nullptr;
#pragma unroll
        for (int mi = 0; mi < 2; mi++) {
            int r = wm + mi * 16 + (lane >> 2);
#pragma unroll
            for (int ni = 0; ni < 8; ni++) {
                int tcol = wn + ni * 8 + 2 * (lane & 3);
                float b0 = sbias[tcol], b1 = sbias[tcol + 1];
                float2 v0 = make_float2(acc[mi][ni][0] + b0, acc[mi][ni][1] + b1);
                float2 v1 = make_float2(acc[mi][ni][2] + b0, acc[mi][ni][3] + b1);
                if (add) {
                    float2 a0 = *(const float2*)&add[(size_t)r * DD + tcol];
                    float2 a1 = *(const float2*)&add[(size_t)(r + 8) * DD + tcol];
                    v0.x += a0.x; v0.y += a0.y;
                    v1.x += a1.x; v1.y += a1.y;
                }
                *(float2*)&outp[(size_t)r * DD + tcol] = v0;
                *(float2*)&outp[(size_t)(r + 8) * DD + tcol] = v1;
            }
        }
    }
}

// ---------------- scores: FP8 e4m3 m16n8k32, exp -> bf16 probs + psum ----
// Stage (bytes): A 128 rows x 80 (64 data) = 10240; B 256 x 80 = 20480.
#define SC_STAGE 30720
#define SC_SMEM  (2 * SC_STAGE + 1024 + 2048)

__global__ __launch_bounds__(256) void scores_f8_kernel(
    const uint8_t* __restrict__ q8,
    const uint8_t* __restrict__ k8,
    const float* __restrict__ cb, __nv_bfloat16* __restrict__ probs,
    float* __restrict__ psum)
{
    extern __shared__ char ssm[];
    float* scb = (float*)(ssm + 2 * SC_STAGE);
    float* sRow = (float*)(ssm + 2 * SC_STAGE + 1024);   // [128][4]
    uint32_t smb = smem_u32(ssm);

    int tid = threadIdx.x;
    int lane = tid & 31, wid = tid >> 5;
    int h = blockIdx.z, bm = blockIdx.y * 128, bn = blockIdx.x * 256;
    int wm = (wid & 1) * 64, wn = (wid >> 1) * 64;

    const uint8_t* A = q8 + ((size_t)h * FF + bm) * DD;
    const uint8_t* B = k8 + (size_t)bn * DD;

    scb[tid] = cb[(size_t)(bn + tid) * HH + h];

    float acc[4][8][4];
#pragma unroll
    for (int mi = 0; mi < 4; mi++)
#pragma unroll
        for (int ni = 0; ni < 8; ni++)
#pragma unroll
            for (int j = 0; j < 4; j++) acc[mi][ni][j] = 0.f;

    int ar = tid >> 2, ac = tid & 3;   // rows 0..63 (x2), 4 x 16B chunks per 64B row

    auto issue = [&](int c, int s) {
        int k0 = c * 64;
        uint32_t sb = smb + s * SC_STAGE;
#pragma unroll
        for (int i = 0; i < 2; i++) {
            int row = ar + i * 64;
            cp16(sb + row * 80 + ac * 16, A + (size_t)row * DD + k0 + ac * 16);
        }
#pragma unroll
        for (int i = 0; i < 4; i++) {
            int row = ar + i * 64;
            cp16(sb + 10240 + row * 80 + ac * 16, B + (size_t)row * DD + k0 + ac * 16);
        }
        CP_COMMIT();
    };

    issue(0, 0);

    for (int c = 0; c < 16; c++) {
        int s = c & 1;
        if (c < 15) issue(c + 1, s ^ 1);
        if (c < 15) { CP_WAIT1(); } else { CP_WAIT0(); }
        __syncthreads();

        const uint8_t* pA = (const uint8_t*)(ssm + s * SC_STAGE);
        const uint8_t* pB = pA + 10240;

#pragma unroll
        for (int ks = 0; ks < 2; ks++) {
            int kb = ks * 32 + 4 * (lane & 3);
            uint32_t ah[4][4];
#pragma unroll
            for (int mi = 0; mi < 4; mi++) {
                int r = wm + mi * 16 + (lane >> 2);
                ah[mi][0] = *(const uint32_t*)&pA[r * 80 + kb];
                ah[mi][1] = *(const uint32_t*)&pA[(r + 8) * 80 + kb];
                ah[mi][2] = *(const uint32_t*)&pA[r * 80 + kb + 16];
                ah[mi][3] = *(const uint32_t*)&pA[(r + 8) * 80 + kb + 16];
            }
#pragma unroll
            for (int ni = 0; ni < 8; ni++) {
                int n = wn + ni * 8 + (lane >> 2);
                uint32_t b0 = *(const uint32_t*)&pB[n * 80 + kb];
                uint32_t b1 = *(const uint32_t*)&pB[n * 80 + kb + 16];
#pragma unroll
                for (int mi = 0; mi < 4; mi++)
                    MMAF8(acc[mi][ni], ah[mi], b0, b1);
            }
        }
        __syncthreads();
    }

    // epilogue: exp(logit) -> bf16 probs, per-row partial sums (deterministic)
    __nv_bfloat16* out = probs + ((size_t)h * FF + bm) * TT + bn;
    float rs[4][2];
#pragma unroll
    for (int mi = 0; mi < 4; mi++) { rs[mi][0] = 0.f; rs[mi][1] = 0.f; }
#pragma unroll
    for (int mi = 0; mi < 4; mi++) {
        int frow = wm + mi * 16 + (lane >> 2);
#pragma unroll
        for (int ni = 0; ni < 8; ni++) {
            int tcol = wn + ni * 8 + 2 * (lane & 3);
            float cb0 = scb[tcol], cb1 = scb[tcol + 1];
            float e0 = __expf((acc[mi][ni][0] + cb0) * SCALE);
            float e1 = __expf((acc[mi][ni][1] + cb1) * SCALE);
            float e2 = __expf((acc[mi][ni][2] + cb0) * SCALE);
            float e3 = __expf((acc[mi][ni][3] + cb1) * SCALE);
            rs[mi][0] += e0 + e1;
            rs[mi][1] += e2 + e3;
            __nv_bfloat162 p0 = __nv_bfloat162(__float2bfloat16(e0), __float2bfloat16(e1));
            __nv_bfloat162 p1 = __nv_bfloat162(__float2bfloat16(e2), __float2bfloat16(e3));
            *(__nv_bfloat162*)&out[(size_t)frow * TT + tcol] = p0;
            *(__nv_bfloat162*)&out[(size_t)(frow + 8) * TT + tcol] = p1;
        }
    }
#pragma unroll
    for (int mi = 0; mi < 4; mi++)
#pragma unroll
        for (int rr = 0; rr < 2; rr++) {
            rs[mi][rr] += __shfl_xor_sync(0xffffffffu, rs[mi][rr], 1);
            rs[mi][rr] += __shfl_xor_sync(0xffffffffu, rs[mi][rr], 2);
        }
    int wnidx = wid >> 1;
    if ((lane & 3) == 0) {
#pragma unroll
        for (int mi = 0; mi < 4; mi++) {
            int r0 = wm + mi * 16 + (lane >> 2);
            sRow[r0 * 4 + wnidx] = rs[mi][0];
            sRow[(r0 + 8) * 4 + wnidx] = rs[mi][1];
        }
    }
    __syncthreads();
    if (tid < 128) {
        float s = sRow[tid * 4 + 0] + sRow[tid * 4 + 1]
                + sRow[tid * 4 + 2] + sRow[tid * 4 + 3];
        psum[((size_t)h * FF + bm + tid) * 8 + blockIdx.x] = s;
    }
}

// ---------------- rinv ----------------
__global__ void rinv_kernel(const float* __restrict__ psum, float* __restrict__ rinv) {
    int i = blockIdx.x * 256 + threadIdx.x;
    float s = 0.f;
#pragma unroll
    for (int j = 0; j < 8; j++) s += psum[(size_t)i * 8 + j];
    rinv[i] = 1.0f / s;
}

// ---------------- ctx: bf16 probs @ vT -> bf16 ctx, double-buffered ------
#define CT_AST 72
#define CT_ASZ (128 * 72 * 2)
#define CT_VSZ (64 * 72 * 2)
#define CT_STAGE (CT_ASZ + CT_VSZ)
#define CT_SMEM (2 * CT_STAGE)

__global__ __launch_bounds__(256, 2) void ctx_db_kernel(
    const __nv_bfloat16* __restrict__ probs, const float* __restrict__ rinv,
    const __nv_bfloat16* __restrict__ vth, __nv_bfloat16* __restrict__ ctxb)
{
    extern __shared__ char csm[];
    uint32_t smb = smem_u32(csm);
    int tid = threadIdx.x;
    int lane = tid & 31, wid = tid >> 5;
    int h = blockIdx.y, bm = blockIdx.x * 128;
    int wm = (wid & 3) * 32, wn = (wid >> 2) * 32;

    const __nv_bfloat16* P = probs + ((size_t)h * FF + bm) * TT;
    const __nv_bfloat16* V = vth + (size_t)h * DH * TT;

    float acc[2][4][4];
#pragma unroll
    for (int mi = 0; mi < 2; mi++)
#pragma unroll
        for (int ni = 0; ni < 4; ni++)
#pragma unroll
            for (int j = 0; j < 4; j++) acc[mi][ni][j] = 0.f;

    int arow = tid >> 3, ac = tid & 7;

    auto issue = [&](int c, int s) {
        int k0 = c * 64;
        uint32_t sb = smb + s * CT_STAGE;
#pragma unroll
        for (int i = 0; i < 4; i++) {
            int row = arow + i * 32;
            cp16(sb + row * 144 + ac * 16, P + (size_t)row * TT + k0 + ac * 8);
        }
#pragma unroll
        for (int i = 0; i < 2; i++) {
            int row = arow + i * 32;
            cp16(sb + CT_ASZ + row * 144 + ac * 16, V + (size_t)row * TT + k0 + ac * 8);
        }
        CP_COMMIT();
    };

    issue(0, 0);

    for (int c = 0; c < 32; c++) {
        int s = c & 1;
        if (c < 31) issue(c + 1, s ^ 1);
        if (c < 31) { CP_WAIT1(); } else { CP_WAIT0(); }
        __syncthreads();

        const __nv_bfloat16* pA = (const __nv_bfloat16*)(csm + s * CT_STAGE);
        const __nv_bfloat16* pV = (const __nv_bfloat16*)(csm + s * CT_STAGE + CT_ASZ);

#pragma unroll
        for (int ks = 0; ks < 4; ks++) {
            int kk = ks * 16 + 2 * (lane & 3);
            uint32_t a[2][4];
#pragma unroll
            for (int mi = 0; mi < 2; mi++) {
                int r = wm + mi * 16 + (lane >> 2);
                a[mi][0] = *(const uint32_t*)&pA[r * CT_AST + kk];
                a[mi][1] = *(const uint32_t*)&pA[(r + 8) * CT_AST + kk];
                a[mi][2] = *(const uint32_t*)&pA[r * CT_AST + kk + 8];
                a[mi][3] = *(const uint32_t*)&pA[(r + 8) * CT_AST + kk + 8];
            }
#pragma unroll
            for (int ni = 0; ni < 4; ni++) {
                int n = wn + ni * 8 + (lane >> 2);
                uint32_t b0 = *(const uint32_t*)&pV[n * CT_AST + kk];
                uint32_t b1 = *(const uint32_t*)&pV[n * CT_AST + kk + 8];
#pragma unroll
                for (int mi = 0; mi < 2; mi++)
                    MMA16816(acc[mi][ni], a[mi], b0, b1);
            }
        }
        __syncthreads();
    }

    const float* rv = rinv + (size_t)h * FF + bm;
    __nv_bfloat16* outp = ctxb + (size_t)bm * DD + h * DH;
#pragma unroll
    for (int mi = 0; mi < 2; mi++) {
        int frow = wm + mi * 16 + (lane >> 2);
        float r0 = rv[frow], r1 = rv[frow + 8];
#pragma unroll
        for (int ni = 0; ni < 4; ni++) {
            int tcol = wn + ni * 8 + 2 * (lane & 3);
            __nv_bfloat162 v0 = __nv_bfloat162(__float2bfloat16(acc[mi][ni][0] * r0),
                                               __float2bfloat16(acc[mi][ni][1] * r0));
            __nv_bfloat162 v1 = __nv_bfloat162(__float2bfloat16(acc[mi][ni][2] * r1),
                                               __float2bfloat16(acc[mi][ni][3] * r1));
            *(__nv_bfloat162*)&outp[(size_t)frow * DD + tcol] = v0;
            *(__nv_bfloat162*)&outp[(size_t)(frow + 8) * DD + tcol] = v1;
        }
    }
}

// ---------------- LayerNorm ----------------
__global__ void ln_kernel(const float* __restrict__ res,
                          const float* __restrict__ gamma,
                          const float* __restrict__ beta,
                          float* __restrict__ out) {
    int r = blockIdx.x;
    const float* row = res + (size_t)r * DD;
    float* orow = out + (size_t)r * DD;
    __shared__ float red[256];
    int tid = threadIdx.x;
    float4 x = *(const float4*)&row[tid * 4];
    float s = x.x + x.y + x.z + x.w;
    red[tid] = s;
    __syncthreads();
    for (int st = 128; st; st >>= 1) {
        if (tid < st) red[tid] += red[tid + st];
        __syncthreads();
    }
    float mean = red[0] * (1.0f / DD);
    __syncthreads();
    float dx = x.x - mean, dy = x.y - mean, dz = x.z - mean, dw = x.w - mean;
    red[tid] = dx * dx + dy * dy + dz * dz + dw * dw;
    __syncthreads();
    for (int st = 128; st; st >>= 1) {
        if (tid < st) red[tid] += red[tid + st];
        __syncthreads();
    }
    float var = red[0] * (1.0f / DD);
    float rstd = rsqrtf(var + kLnEps);
    float4 g = *(const float4*)&gamma[tid * 4];
    float4 b = *(const float4*)&beta[tid * 4];
    float4 o;
    o.x = dx * rstd * g.x + b.x;
    o.y = dy * rstd * g.y + b.y;
    o.z = dz * rstd * g.z + b.z;
    o.w = dw * rstd * g.w + b.w;
    *(float4*)&orow[tid * 4] = o;
}

// ---------------- launch ----------------
extern "C" void kernel_launch(void* const* d_in, const int* in_sizes, int n_in,
                              void* d_out, int out_size) {
    const float* hidden = (const float*)d_in[0];
    const int* fpos = (const int*)d_in[1];
    const int* tpos = (const int*)d_in[2];
    const float* Wq = (const float*)d_in[3];
    const float* Wk = (const float*)d_in[4];
    const float* Wcb = (const float*)d_in[5];
    const float* Wv = (const float*)d_in[6];
    const float* bv = (const float*)d_in[7];
    const float* mixing = (const float*)d_in[8];
    const float* Wd = (const float*)d_in[9];
    const float* bd = (const float*)d_in[10];
    const float* gamma = (const float*)d_in[11];
    const float* beta = (const float*)d_in[12];
    float* out = (float*)d_out;

    float *p_from, *p_to, *p_q, *p_v, *p_cb, *p_scores, *p_res;
    float *p_psum, *p_rinv;
    uint8_t *p_q8, *p_k8;
    __nv_bfloat16 *p_fh, *p_th, *p_ch;
    __nv_bfloat16 *p_wqh, *p_wkh, *p_wvh, *p_wdh, *p_vth;
    cudaGetSymbolAddress((void**)&p_from, g_from);
    cudaGetSymbolAddress((void**)&p_to, g_to);
    cudaGetSymbolAddress((void**)&p_q, g_q);
    cudaGetSymbolAddress((void**)&p_v, g_v);
    cudaGetSymbolAddress((void**)&p_cb, g_cb);
    cudaGetSymbolAddress((void**)&p_scores, g_scores);
    cudaGetSymbolAddress((void**)&p_res, g_res);
    cudaGetSymbolAddress((void**)&p_psum, g_psum);
    cudaGetSymbolAddress((void**)&p_rinv, g_rinv);
    cudaGetSymbolAddress((void**)&p_q8, g_q8);
    cudaGetSymbolAddress((void**)&p_k8, g_k8);
    cudaGetSymbolAddress((void**)&p_fh, g_fh);
    cudaGetSymbolAddress((void**)&p_th, g_th);
    cudaGetSymbolAddress((void**)&p_ch, g_ch);
    cudaGetSymbolAddress((void**)&p_wqh, g_wqh);
    cudaGetSymbolAddress((void**)&p_wkh, g_wkh);
    cudaGetSymbolAddress((void**)&p_wvh, g_wvh);
    cudaGetSymbolAddress((void**)&p_wdh, g_wdh);
    cudaGetSymbolAddress((void**)&p_vth, g_vth);

    __nv_bfloat16* p_probs = (__nv_bfloat16*)p_scores;

    cudaFuncSetAttribute(scores_f8_kernel,
                         cudaFuncAttributeMaxDynamicSharedMemorySize, SC_SMEM);
    cudaFuncSetAttribute(gemm_sp_kernel,
                         cudaFuncAttributeMaxDynamicSharedMemorySize, GM_SMEM);
    cudaFuncSetAttribute(ctx_db_kernel,
                         cudaFuncAttributeMaxDynamicSharedMemorySize, CT_SMEM);

    dim3 tb(32, 8);
    dim3 tgW(DD / 32, DD / 32);

    gather_kernel<<<FF, 256>>>(hidden, fpos, tpos);
    transpose_h_kernel<<<tgW, tb>>>(Wq, DD, DD, p_wqh);
    transpose_h_kernel<<<tgW, tb>>>(Wk, DD, DD, p_wkh);
    transpose_h_kernel<<<tgW, tb>>>(Wv, DD, DD, p_wvh);
    transpose_h_kernel<<<tgW, tb>>>(Wd, DD, DD, p_wdh);

    dim3 gg(DD / 128, FF / 128);
    gemm_sp_kernel<<<gg, 256, GM_SMEM>>>(p_fh, p_wqh, nullptr, nullptr, p_q, nullptr);
    gemm_sp_kernel<<<gg, 256, GM_SMEM>>>(p_th, p_wkh, nullptr, nullptr, nullptr, p_k8);
    gemm_sp_kernel<<<gg, 256, GM_SMEM>>>(p_th, p_wvh, bv, nullptr, p_v, nullptr);
    cb_kernel<<<TT, 256>>>(Wcb, p_cb);

    split_q_kernel<<<HH * FF, 256>>>(p_q, mixing, p_q8);
    transpose_h_kernel<<<dim3(DD / 32, TT / 32), tb>>>(p_v, TT, DD, p_vth);

    scores_f8_kernel<<<dim3(TT / 256, FF / 128, HH), 256, SC_SMEM>>>(
        p_q8, p_k8, p_cb, p_probs, p_psum);

    rinv_kernel<<<HH * FF / 256, 256>>>(p_psum, p_rinv);
    ctx_db_kernel<<<dim3(FF / 128, HH), 256, CT_SMEM>>>(p_probs, p_rinv, p_vth, p_ch);

    gemm_sp_kernel<<<gg, 256, GM_SMEM>>>(p_ch, p_wdh, bd, p_from, p_res, nullptr);
    ln_kernel<<<FF, 256>>>(p_res, gamma, beta, out);
    (void)in_sizes; (void)n_in; (void)out_size;
}

// round 15
// speedup vs baseline: 1.1280x; 1.1280x over previous
#include <cuda_runtime.h>
#include <cuda_bf16.h>
#include <cstdint>
#include <math.h>

#define HH 16
#define DD 1024
#define DH 64
#define FF 2048
#define TT 2048
#define SS 512

static __constant__ float kLnEps = 1e-5f;
#define SCALE 0.125f  /* 1/sqrt(1024/16) = 1/8 */

// ---------------- scratch (device globals, no allocations) ----------------
__device__ float g_from[FF * DD];
__device__ float g_to[TT * DD];
__device__ float g_q[FF * DD];
__device__ float g_v[TT * DD];
__device__ float g_cb[TT * HH];
__device__ float g_scores[(size_t)HH * FF * TT];   // reused as bf16 probs
__device__ float g_res[FF * DD];
__device__ float g_psum[(size_t)HH * FF * 8];
__device__ float g_rinv[HH * FF];
__device__ __nv_bfloat16 g_qh[(size_t)HH * FF * DD];
__device__ __nv_bfloat16 g_kh[(size_t)TT * DD];
__device__ __nv_bfloat16 g_fh[(size_t)FF * DD];
__device__ __nv_bfloat16 g_th[(size_t)TT * DD];
__device__ __nv_bfloat16 g_ch[(size_t)FF * DD];
__device__ __nv_bfloat16 g_wqh[(size_t)DD * DD];
__device__ __nv_bfloat16 g_wkh[(size_t)DD * DD];
__device__ __nv_bfloat16 g_wvh[(size_t)DD * DD];
__device__ __nv_bfloat16 g_wdh[(size_t)DD * DD];
__device__ __nv_bfloat16 g_vth[(size_t)DD * TT];

// mma.sync m16n8k16 bf16 (portable HMMA; tcgen05 PTX rejected by compute_103)
#define MMA16816(d, a, b0, b1)                                              \
    asm volatile(                                                           \
        "mma.sync.aligned.m16n8k16.row.col.f32.bf16.bf16.f32 "              \
        "{%0,%1,%2,%3}, {%4,%5,%6,%7}, {%8,%9}, {%0,%1,%2,%3};"             \
        : "+f"((d)[0]), "+f"((d)[1]), "+f"((d)[2]), "+f"((d)[3])            \
        : "r"((a)[0]), "r"((a)[1]), "r"((a)[2]), "r"((a)[3]),               \
          "r"(b0), "r"(b1))

__device__ __forceinline__ uint32_t smem_u32(const void* p) {
    uint32_t a;
    asm("{ .reg .u64 t; cvta.to.shared.u64 t, %1; cvt.u32.u64 %0, t; }" : "=r"(a) : "l"(p));
    return a;
}
__device__ __forceinline__ void cp16(uint32_t dst, const void* src) {
    asm volatile("cp.async.cg.shared.global [%0], [%1], 16;" :: "r"(dst), "l"(src));
}
#define CP_COMMIT() asm volatile("cp.async.commit_group;" ::: "memory")
#define CP_WAIT2()  asm volatile("cp.async.wait_group 2;" ::: "memory")
#define CP_WAIT1()  asm volatile("cp.async.wait_group 1;" ::: "memory")
#define CP_WAIT0()  asm volatile("cp.async.wait_group 0;" ::: "memory")

// ---------------- gather (also emits bf16 planes) ----------------
__global__ void gather_kernel(const float* __restrict__ hidden,
                              const int* __restrict__ fpos,
                              const int* __restrict__ tpos) {
    int row = blockIdx.x;
    int fi = fpos[row] & (SS - 1);
    int ti = tpos[row] & (SS - 1);
    const float4* srcf = (const float4*)(hidden + (size_t)fi * DD);
    const float4* srct = (const float4*)(hidden + (size_t)ti * DD);
    float4* dstf = (float4*)(g_from + (size_t)row * DD);
    float4* dstt = (float4*)(g_to + (size_t)row * DD);
    for (int i = threadIdx.x; i < DD / 4; i += blockDim.x) {
        float4 f = srcf[i];
        float4 t = srct[i];
        dstf[i] = f;
        dstt[i] = t;
        size_t o = (size_t)row * DD + i * 4;
        *(__nv_bfloat162*)&g_fh[o]     = __nv_bfloat162(__float2bfloat16(f.x), __float2bfloat16(f.y));
        *(__nv_bfloat162*)&g_fh[o + 2] = __nv_bfloat162(__float2bfloat16(f.z), __float2bfloat16(f.w));
        *(__nv_bfloat162*)&g_th[o]     = __nv_bfloat162(__float2bfloat16(t.x), __float2bfloat16(t.y));
        *(__nv_bfloat162*)&g_th[o + 2] = __nv_bfloat162(__float2bfloat16(t.z), __float2bfloat16(t.w));
    }
}

// ---------------- batched weight transpose: 4 weights in one launch ------
__global__ void transpose_w4_kernel(const float* __restrict__ w0, const float* __restrict__ w1,
                                    const float* __restrict__ w2, const float* __restrict__ w3,
                                    __nv_bfloat16* __restrict__ o0, __nv_bfloat16* __restrict__ o1,
                                    __nv_bfloat16* __restrict__ o2, __nv_bfloat16* __restrict__ o3) {
    const float* in = (blockIdx.z == 0) ? w0 : (blockIdx.z == 1) ? w1 : (blockIdx.z == 2) ? w2 : w3;
    __nv_bfloat16* oh = (blockIdx.z == 0) ? o0 : (blockIdx.z == 1) ? o1 : (blockIdx.z == 2) ? o2 : o3;
    __shared__ float t[32][33];
    int bc = blockIdx.x * 32, br = blockIdx.y * 32;
    int tx = threadIdx.x, ty = threadIdx.y;   // 32 x 8
#pragma unroll
    for (int j = 0; j < 32; j += 8)
        t[ty + j][tx] = in[(size_t)(br + ty + j) * DD + bc + tx];
    __syncthreads();
#pragma unroll
    for (int j = 0; j < 32; j += 8)
        oh[(size_t)(bc + ty + j) * DD + br + tx] = __float2bfloat16(t[tx][ty + j]);
}

// ---------------- transpose (hi only): in[R,C] fp32 -> out[C][R] bf16 ----
__global__ void transpose_h_kernel(const float* __restrict__ in, int R, int C,
                                   __nv_bfloat16* __restrict__ oh) {
    __shared__ float t[32][33];
    int bc = blockIdx.x * 32, br = blockIdx.y * 32;
    int tx = threadIdx.x, ty = threadIdx.y;   // 32 x 8
#pragma unroll
    for (int j = 0; j < 32; j += 8)
        t[ty + j][tx] = in[(size_t)(br + ty + j) * C + bc + tx];
    __syncthreads();
#pragma unroll
    for (int j = 0; j < 32; j += 8)
        oh[(size_t)(bc + ty + j) * R + br + tx] = __float2bfloat16(t[tx][ty + j]);
}

// ---------------- cb ----------------
__global__ void cb_kernel(const float* __restrict__ Wcb, float* __restrict__ cb) {
    int t = blockIdx.x;
    int lane = threadIdx.x & 31, w = threadIdx.x >> 5;
    const float* row = g_to + (size_t)t * DD;
#pragma unroll
    for (int hh = 0; hh < 2; hh++) {
        int h = w * 2 + hh;
        float s = 0.f;
        for (int d = lane; d < DD; d += 32) s += row[d] * Wcb[d * HH + h];
#pragma unroll
        for (int o = 16; o; o >>= 1) s += __shfl_down_sync(0xffffffffu, s, o);
        if (lane == 0) cb[t * HH + h] = s;
    }
}

// ---------------- split mixed-q (bf16) ----------------
__global__ void split_q_kernel(const float* __restrict__ q, const float* __restrict__ mixing,
                               __nv_bfloat16* __restrict__ qh) {
    int h = blockIdx.x >> 11;
    int f = blockIdx.x & (FF - 1);
    int d = threadIdx.x * 4;
    float4 x = *(const float4*)&q[(size_t)f * DD + d];
    float4 m = *(const float4*)&mixing[(size_t)h * DD + d];
    size_t o = ((size_t)h * FF + f) * DD + d;
    *(__nv_bfloat162*)&qh[o]     = __nv_bfloat162(__float2bfloat16(x.x * m.x), __float2bfloat16(x.y * m.y));
    *(__nv_bfloat162*)&qh[o + 2] = __nv_bfloat162(__float2bfloat16(x.z * m.z), __float2bfloat16(x.w * m.w));
}

// ---------------- dense GEMM, single-product bf16, 4-stage pipeline ------
#define GM_STAGE 20480
#define GM_SMEM  (4 * GM_STAGE + 128 * 4)

__global__ __launch_bounds__(256) void gemm_sp_kernel(
    const __nv_bfloat16* __restrict__ Ah_,
    const __nv_bfloat16* __restrict__ Bh_,
    const float* __restrict__ bias, const float* __restrict__ addend,
    float* __restrict__ C, __nv_bfloat16* __restrict__ Cbf)
{
    extern __shared__ char gsm[];
    float* sbias = (float*)(gsm + 4 * GM_STAGE);
    uint32_t smb = smem_u32(gsm);

    int tid = threadIdx.x;
    int lane = tid & 31, wid = tid >> 5;
    int bm = blockIdx.y * 128, bn = blockIdx.x * 128;
    int wm = (wid & 3) * 32, wn = (wid >> 2) * 64;

    const __nv_bfloat16* Ah = Ah_ + (size_t)bm * DD;
    const __nv_bfloat16* Bh = Bh_ + (size_t)bn * DD;

    if (tid < 128) sbias[tid] = bias ? bias[bn + tid] : 0.f;

    float acc[2][8][4];
#pragma unroll
    for (int mi = 0; mi < 2; mi++)
#pragma unroll
        for (int ni = 0; ni < 8; ni++)
#pragma unroll
            for (int j = 0; j < 4; j++) acc[mi][ni][j] = 0.f;

    int frow = tid >> 1;
    int fc = (tid & 1) * 16;
    uint32_t fb = frow * 80 + (tid & 1) * 32;

    auto issue = [&](int c) {
        int s = c & 3;
        int k0 = c * 32;
        uint32_t sb = smb + s * GM_STAGE;
        size_t go = (size_t)frow * DD + k0 + fc;
        uint32_t d = sb + fb;
        cp16(d, Ah + go);               cp16(d + 16, Ah + go + 8);
        cp16(d + 10240, Bh + go);       cp16(d + 10240 + 16, Bh + go + 8);
        CP_COMMIT();
    };

    issue(0); issue(1);

    for (int c = 0; c < 32; c++) {
        if (c + 2 < 32) issue(c + 2);
        if (c < 30) { CP_WAIT2(); } else if (c == 30) { CP_WAIT1(); } else { CP_WAIT0(); }
        __syncthreads();

        const __nv_bfloat16* pAh = (const __nv_bfloat16*)(gsm + (c & 3) * GM_STAGE);
        const __nv_bfloat16* pBh = pAh + 5120;

#pragma unroll
        for (int ks = 0; ks < 2; ks++) {
            int kk = ks * 16 + 2 * (lane & 3);
            uint32_t ah[2][4];
#pragma unroll
            for (int mi = 0; mi < 2; mi++) {
                int r = wm + mi * 16 + (lane >> 2);
                ah[mi][0] = *(const uint32_t*)&pAh[r * 40 + kk];
                ah[mi][1] = *(const uint32_t*)&pAh[(r + 8) * 40 + kk];
                ah[mi][2] = *(const uint32_t*)&pAh[r * 40 + kk + 8];
                ah[mi][3] = *(const uint32_t*)&pAh[(r + 8) * 40 + kk + 8];
            }
#pragma unroll
            for (int ni = 0; ni < 8; ni++) {
                int n = wn + ni * 8 + (lane >> 2);
                uint32_t bh0 = *(const uint32_t*)&pBh[n * 40 + kk];
                uint32_t bh1 = *(const uint32_t*)&pBh[n * 40 + kk + 8];
#pragma unroll
                for (int mi = 0; mi < 2; mi++)
                    MMA16816(acc[mi][ni], ah[mi], bh0, bh1);
            }
        }
    }

    if (Cbf) {
        __nv_bfloat16* ob = Cbf + (size_t)bm * DD + bn;
#pragma unroll
        for (int mi = 0; mi < 2; mi++) {
            int r = wm + mi * 16 + (lane >> 2);
#pragma unroll
            for (int ni = 0; ni < 8; ni++) {
                int tcol = wn + ni * 8 + 2 * (lane & 3);
                float b0 = sbias[tcol], b1 = sbias[tcol + 1];
                __nv_bfloat162 v0 = __nv_bfloat162(__float2bfloat16(acc[mi][ni][0] + b0),
                                                   __float2bfloat16(acc[mi][ni][1] + b1));
                __nv_bfloat162 v1 = __nv_bfloat162(__float2bfloat16(acc[mi][ni][2] + b0),
                                                   __float2bfloat16(acc[mi][ni][3] + b1));
                *(__nv_bfloat162*)&ob[(size_t)r * DD + tcol] = v0;
                *(__nv_bfloat162*)&ob[(size_t)(r + 8) * DD + tcol] = v1;
            }
        }
    } else {
        float* outp = C + (size_t)bm * DD + bn;
        const float* add = addend ? addend + (size_t)bm * DD + bn : nullptr;
#pragma unroll
        for (int mi = 0; mi < 2; mi++) {
            int r = wm + mi * 16 + (lane >> 2);
#pragma unroll
            for (int ni = 0; ni < 8; ni++) {
                int tcol = wn + ni * 8 + 2 * (lane & 3);
                float b0 = sbias[tcol], b1 = sbias[tcol + 1];
                float2 v0 = make_float2(acc[mi][ni][0] + b0, acc[mi][ni][1] + b1);
                float2 v1 = make_float2(acc[mi][ni][2] + b0, acc[mi][ni][3] + b1);
                if (add) {
                    float2 a0 = *(const float2*)&add[(size_t)r * DD + tcol];
                    float2 a1 = *(const float2*)&add[(size_t)(r + 8) * DD + tcol];
                    v0.x += a0.x; v0.y += a0.y;
                    v1.x += a1.x; v1.y += a1.y;
                }
                *(float2*)&outp[(size_t)r * DD + tcol] = v0;
                *(float2*)&outp[(size_t)(r + 8) * DD + tcol] = v1;
            }
        }
    }
}

// ---------------- scores: single-product bf16, 4-stage, one sync/chunk ---
#define SC_STAGE 30720
#define SC_SMEM  (4 * SC_STAGE + 1024 + 2048)

__global__ __launch_bounds__(256) void scores_db_kernel(
    const __nv_bfloat16* __restrict__ qh,
    const __nv_bfloat16* __restrict__ kh,
    const float* __restrict__ cb, __nv_bfloat16* __restrict__ probs,
    float* __restrict__ psum)
{
    extern __shared__ char ssm[];
    float* scb = (float*)(ssm + 4 * SC_STAGE);
    float* sRow = (float*)(ssm + 4 * SC_STAGE + 1024);   // [128][4]
    uint32_t smb = smem_u32(ssm);

    int tid = threadIdx.x;
    int lane = tid & 31, wid = tid >> 5;
    int h = blockIdx.z, bm = blockIdx.y * 128, bn = blockIdx.x * 256;
    int wm = (wid & 1) * 64, wn = (wid >> 1) * 64;

    const __nv_bfloat16* Ah = qh + ((size_t)h * FF + bm) * DD;
    const __nv_bfloat16* Bh = kh + (size_t)bn * DD;

    scb[tid] = cb[(size_t)(bn + tid) * HH + h];

    float acc[4][8][4];
#pragma unroll
    for (int mi = 0; mi < 4; mi++)
#pragma unroll
        for (int ni = 0; ni < 8; ni++)
#pragma unroll
            for (int j = 0; j < 4; j++) acc[mi][ni][j] = 0.f;

    int ar = tid >> 2, ac = tid & 3;

    auto issue = [&](int c) {
        int s = c & 3;
        int k0 = c * 32;
        uint32_t sb = smb + s * SC_STAGE;
#pragma unroll
        for (int i = 0; i < 2; i++) {
            int row = ar + i * 64;
            cp16(sb + row * 80 + ac * 16, Ah + (size_t)row * DD + k0 + ac * 8);
        }
#pragma unroll
        for (int i = 0; i < 4; i++) {
            int row = ar + i * 64;
            cp16(sb + 10240 + row * 80 + ac * 16, Bh + (size_t)row * DD + k0 + ac * 8);
        }
        CP_COMMIT();
    };

    issue(0); issue(1);

    for (int c = 0; c < 32; c++) {
        if (c + 2 < 32) issue(c + 2);
        if (c < 30) { CP_WAIT2(); } else if (c == 30) { CP_WAIT1(); } else { CP_WAIT0(); }
        __syncthreads();

        const __nv_bfloat16* pAh = (const __nv_bfloat16*)(ssm + (c & 3) * SC_STAGE);
        const __nv_bfloat16* pBh = pAh + 5120;

#pragma unroll
        for (int ks = 0; ks < 2; ks++) {
            int kk = ks * 16 + 2 * (lane & 3);
            uint32_t ah[4][4];
#pragma unroll
            for (int mi = 0; mi < 4; mi++) {
                int r = wm + mi * 16 + (lane >> 2);
                ah[mi][0] = *(const uint32_t*)&pAh[r * 40 + kk];
                ah[mi][1] = *(const uint32_t*)&pAh[(r + 8) * 40 + kk];
                ah[mi][2] = *(const uint32_t*)&pAh[r * 40 + kk + 8];
                ah[mi][3] = *(const uint32_t*)&pAh[(r + 8) * 40 + kk + 8];
            }
#pragma unroll
            for (int ni = 0; ni < 8; ni++) {
                int n = wn + ni * 8 + (lane >> 2);
                uint32_t bh0 = *(const uint32_t*)&pBh[n * 40 + kk];
                uint32_t bh1 = *(const uint32_t*)&pBh[n * 40 + kk + 8];
#pragma unroll
                for (int mi = 0; mi < 4; mi++)
                    MMA16816(acc[mi][ni], ah[mi], bh0, bh1);
            }
        }
    }

    // epilogue: exp(logit) -> bf16 probs, per-row partial sums (deterministic)
    __nv_bfloat16* out = probs + ((size_t)h * FF + bm) * TT + bn;
    float rs[4][2];
#pragma unroll
    for (int mi = 0; mi < 4; mi++) { rs[mi][0] = 0.f; rs[mi][1] = 0.f; }
#pragma unroll
    for (int mi = 0; mi < 4; mi++) {
        int frow = wm + mi * 16 + (lane >> 2);
#pragma unroll
        for (int ni = 0; ni < 8; ni++) {
            int tcol = wn + ni * 8 + 2 * (lane & 3);
            float cb0 = scb[tcol], cb1 = scb[tcol + 1];
            float e0 = __expf((acc[mi][ni][0] + cb0) * SCALE);
            float e1 = __expf((acc[mi][ni][1] + cb1) * SCALE);
            float e2 = __expf((acc[mi][ni][2] + cb0) * SCALE);
            float e3 = __expf((acc[mi][ni][3] + cb1) * SCALE);
            rs[mi][0] += e0 + e1;
            rs[mi][1] += e2 + e3;
            __nv_bfloat162 p0 = __nv_bfloat162(__float2bfloat16(e0), __float2bfloat16(e1));
            __nv_bfloat162 p1 = __nv_bfloat162(__float2bfloat16(e2), __float2bfloat16(e3));
            *(__nv_bfloat162*)&out[(size_t)frow * TT + tcol] = p0;
            *(__nv_bfloat162*)&out[(size_t)(frow + 8) * TT + tcol] = p1;
        }
    }
#pragma unroll
    for (int mi = 0; mi < 4; mi++)
#pragma unroll
        for (int rr = 0; rr < 2; rr++) {
            rs[mi][rr] += __shfl_xor_sync(0xffffffffu, rs[mi][rr], 1);
            rs[mi][rr] += __shfl_xor_sync(0xffffffffu, rs[mi][rr], 2);
        }
    int wnidx = wid >> 1;
    __syncthreads();   // acc reads of smem stages done; reuse sRow region safely
    if ((lane & 3) == 0) {
#pragma unroll
        for (int mi = 0; mi < 4; mi++) {
            int r0 = wm + mi * 16 + (lane >> 2);
            sRow[r0 * 4 + wnidx] = rs[mi][0];
            sRow[(r0 + 8) * 4 + wnidx] = rs[mi][1];
        }
    }
    __syncthreads();
    if (tid < 128) {
        float s = sRow[tid * 4 + 0] + sRow[tid * 4 + 1]
                + sRow[tid * 4 + 2] + sRow[tid * 4 + 3];
        psum[((size_t)h * FF + bm + tid) * 8 + blockIdx.x] = s;
    }
}

// ---------------- rinv ----------------
__global__ void rinv_kernel(const float* __restrict__ psum, float* __restrict__ rinv) {
    int i = blockIdx.x * 256 + threadIdx.x;
    float s = 0.f;
#pragma unroll
    for (int j = 0; j < 8; j++) s += psum[(size_t)i * 8 + j];
    rinv[i] = 1.0f / s;
}

// ---------------- ctx: bf16 probs @ vT -> bf16, 3-stage, one sync/chunk --
#define CT_AST 72
#define CT_ASZ (128 * 72 * 2)
#define CT_VSZ (64 * 72 * 2)
#define CT_STAGE (CT_ASZ + CT_VSZ)
#define CT_SMEM (3 * CT_STAGE)

__global__ __launch_bounds__(256) void ctx_db_kernel(
    const __nv_bfloat16* __restrict__ probs, const float* __restrict__ rinv,
    const __nv_bfloat16* __restrict__ vth, __nv_bfloat16* __restrict__ ctxb)
{
    extern __shared__ char csm[];
    uint32_t smb = smem_u32(csm);
    int tid = threadIdx.x;
    int lane = tid & 31, wid = tid >> 5;
    int h = blockIdx.y, bm = blockIdx.x * 128;
    int wm = (wid & 3) * 32, wn = (wid >> 2) * 32;

    const __nv_bfloat16* P = probs + ((size_t)h * FF + bm) * TT;
    const __nv_bfloat16* V = vth + (size_t)h * DH * TT;

    float acc[2][4][4];
#pragma unroll
    for (int mi = 0; mi < 2; mi++)
#pragma unroll
        for (int ni = 0; ni < 4; ni++)
#pragma unroll
            for (int j = 0; j < 4; j++) acc[mi][ni][j] = 0.f;

    int arow = tid >> 3, ac = tid & 7;

    auto issue = [&](int c) {
        int s = c % 3;
        int k0 = c * 64;
        uint32_t sb = smb + s * CT_STAGE;
#pragma unroll
        for (int i = 0; i < 4; i++) {
            int row = arow + i * 32;
            cp16(sb + row * 144 + ac * 16, P + (size_t)row * TT + k0 + ac * 8);
        }
#pragma unroll
        for (int i = 0; i < 2; i++) {
            int row = arow + i * 32;
            cp16(sb + CT_ASZ + row * 144 + ac * 16, V + (size_t)row * TT + k0 + ac * 8);
        }
        CP_COMMIT();
    };

    issue(0);

    for (int c = 0; c < 32; c++) {
        if (c + 1 < 32) issue(c + 1);
        if (c < 31) { CP_WAIT1(); } else { CP_WAIT0(); }
        __syncthreads();

        const __nv_bfloat16* pA = (const __nv_bfloat16*)(csm + (c % 3) * CT_STAGE);
        const __nv_bfloat16* pV = (const __nv_bfloat16*)((const char*)pA + CT_ASZ);

#pragma unroll
        for (int ks = 0; ks < 4; ks++) {
            int kk = ks * 16 + 2 * (lane & 3);
            uint32_t a[2][4];
#pragma unroll
            for (int mi = 0; mi < 2; mi++) {
                int r = wm + mi * 16 + (lane >> 2);
                a[mi][0] = *(const uint32_t*)&pA[r * CT_AST + kk];
                a[mi][1] = *(const uint32_t*)&pA[(r + 8) * CT_AST + kk];
                a[mi][2] = *(const uint32_t*)&pA[r * CT_AST + kk + 8];
                a[mi][3] = *(const uint32_t*)&pA[(r + 8) * CT_AST + kk + 8];
            }
#pragma unroll
            for (int ni = 0; ni < 4; ni++) {
                int n = wn + ni * 8 + (lane >> 2);
                uint32_t b0 = *(const uint32_t*)&pV[n * CT_AST + kk];
                uint32_t b1 = *(const uint32_t*)&pV[n * CT_AST + kk + 8];
#pragma unroll
                for (int mi = 0; mi < 2; mi++)
                    MMA16816(acc[mi][ni], a[mi], b0, b1);
            }
        }
    }

    const float* rv = rinv + (size_t)h * FF + bm;
    __nv_bfloat16* outp = ctxb + (size_t)bm * DD + h * DH;
#pragma unroll
    for (int mi = 0; mi < 2; mi++) {
        int frow = wm + mi * 16 + (lane >> 2);
        float r0 = rv[frow], r1 = rv[frow + 8];
#pragma unroll
        for (int ni = 0; ni < 4; ni++) {
            int tcol = wn + ni * 8 + 2 * (lane & 3);
            __nv_bfloat162 v0 = __nv_bfloat162(__float2bfloat16(acc[mi][ni][0] * r0),
                                               __float2bfloat16(acc[mi][ni][1] * r0));
            __nv_bfloat162 v1 = __nv_bfloat162(__float2bfloat16(acc[mi][ni][2] * r1),
                                               __float2bfloat16(acc[mi][ni][3] * r1));
            *(__nv_bfloat162*)&outp[(size_t)frow * DD + tcol] = v0;
            *(__nv_bfloat162*)&outp[(size_t)(frow + 8) * DD + tcol] = v1;
        }
    }
}

// ---------------- LayerNorm ----------------
__global__ void ln_kernel(const float* __restrict__ res,
                          const float* __restrict__ gamma,
                          const float* __restrict__ beta,
                          float* __restrict__ out) {
    int r = blockIdx.x;
    const float* row = res + (size_t)r * DD;
    float* orow = out + (size_t)r * DD;
    __shared__ float red[256];
    int tid = threadIdx.x;
    float4 x = *(const float4*)&row[tid * 4];
    float s = x.x + x.y + x.z + x.w;
    red[tid] = s;
    __syncthreads();
    for (int st = 128; st; st >>= 1) {
        if (tid < st) red[tid] += red[tid + st];
        __syncthreads();
    }
    float mean = red[0] * (1.0f / DD);
    __syncthreads();
    float dx = x.x - mean, dy = x.y - mean, dz = x.z - mean, dw = x.w - mean;
    red[tid] = dx * dx + dy * dy + dz * dz + dw * dw;
    __syncthreads();
    for (int st = 128; st; st >>= 1) {
        if (tid < st) red[tid] += red[tid + st];
        __syncthreads();
    }
    float var = red[0] * (1.0f / DD);
    float rstd = rsqrtf(var + kLnEps);
    float4 g = *(const float4*)&gamma[tid * 4];
    float4 b = *(const float4*)&beta[tid * 4];
    float4 o;
    o.x = dx * rstd * g.x + b.x;
    o.y = dy * rstd * g.y + b.y;
    o.z = dz * rstd * g.z + b.z;
    o.w = dw * rstd * g.w + b.w;
    *(float4*)&orow[tid * 4] = o;
}

// ---------------- launch ----------------
extern "C" void kernel_launch(void* const* d_in, const int* in_sizes, int n_in,
                              void* d_out, int out_size) {
    const float* hidden = (const float*)d_in[0];
    const int* fpos = (const int*)d_in[1];
    const int* tpos = (const int*)d_in[2];
    const float* Wq = (const float*)d_in[3];
    const float* Wk = (const float*)d_in[4];
    const float* Wcb = (const float*)d_in[5];
    const float* Wv = (const float*)d_in[6];
    const float* bv = (const float*)d_in[7];
    const float* mixing = (const float*)d_in[8];
    const float* Wd = (const float*)d_in[9];
    const float* bd = (const float*)d_in[10];
    const float* gamma = (const float*)d_in[11];
    const float* beta = (const float*)d_in[12];
    float* out = (float*)d_out;

    float *p_from, *p_to, *p_q, *p_v, *p_cb, *p_scores, *p_res;
    float *p_psum, *p_rinv;
    __nv_bfloat16 *p_qh, *p_kh;
    __nv_bfloat16 *p_fh, *p_th, *p_ch;
    __nv_bfloat16 *p_wqh, *p_wkh, *p_wvh, *p_wdh, *p_vth;
    cudaGetSymbolAddress((void**)&p_from, g_from);
    cudaGetSymbolAddress((void**)&p_to, g_to);
    cudaGetSymbolAddress((void**)&p_q, g_q);
    cudaGetSymbolAddress((void**)&p_v, g_v);
    cudaGetSymbolAddress((void**)&p_cb, g_cb);
    cudaGetSymbolAddress((void**)&p_scores, g_scores);
    cudaGetSymbolAddress((void**)&p_res, g_res);
    cudaGetSymbolAddress((void**)&p_psum, g_psum);
    cudaGetSymbolAddress((void**)&p_rinv, g_rinv);
    cudaGetSymbolAddress((void**)&p_qh, g_qh);
    cudaGetSymbolAddress((void**)&p_kh, g_kh);
    cudaGetSymbolAddress((void**)&p_fh, g_fh);
    cudaGetSymbolAddress((void**)&p_th, g_th);
    cudaGetSymbolAddress((void**)&p_ch, g_ch);
    cudaGetSymbolAddress((void**)&p_wqh, g_wqh);
    cudaGetSymbolAddress((void**)&p_wkh, g_wkh);
    cudaGetSymbolAddress((void**)&p_wvh, g_wvh);
    cudaGetSymbolAddress((void**)&p_wdh, g_wdh);
    cudaGetSymbolAddress((void**)&p_vth, g_vth);

    __nv_bfloat16* p_probs = (__nv_bfloat16*)p_scores;

    cudaFuncSetAttribute(scores_db_kernel,
                         cudaFuncAttributeMaxDynamicSharedMemorySize, SC_SMEM);
    cudaFuncSetAttribute(gemm_sp_kernel,
                         cudaFuncAttributeMaxDynamicSharedMemorySize, GM_SMEM);
    cudaFuncSetAttribute(ctx_db_kernel,
                         cudaFuncAttributeMaxDynamicSharedMemorySize, CT_SMEM);

    dim3 tb(32, 8);

    gather_kernel<<<FF, 256>>>(hidden, fpos, tpos);
    transpose_w4_kernel<<<dim3(DD / 32, DD / 32, 4), tb>>>(
        Wq, Wk, Wv, Wd, p_wqh, p_wkh, p_wvh, p_wdh);

    dim3 gg(DD / 128, FF / 128);
    gemm_sp_kernel<<<gg, 256, GM_SMEM>>>(p_fh, p_wqh, nullptr, nullptr, p_q, nullptr);
    gemm_sp_kernel<<<gg, 256, GM_SMEM>>>(p_th, p_wkh, nullptr, nullptr, nullptr, p_kh);
    gemm_sp_kernel<<<gg, 256, GM_SMEM>>>(p_th, p_wvh, bv, nullptr, p_v, nullptr);
    cb_kernel<<<TT, 256>>>(Wcb, p_cb);

    split_q_kernel<<<HH * FF, 256>>>(p_q, mixing, p_qh);
    transpose_h_kernel<<<dim3(DD / 32, TT / 32), tb>>>(p_v, TT, DD, p_vth);

    scores_db_kernel<<<dim3(TT / 256, FF / 128, HH), 256, SC_SMEM>>>(
        p_qh, p_kh, p_cb, p_probs, p_psum);

    rinv_kernel<<<HH * FF / 256, 256>>>(p_psum, p_rinv);
    ctx_db_kernel<<<dim3(FF / 128, HH), 256, CT_SMEM>>>(p_probs, p_rinv, p_vth, p_ch);

    gemm_sp_kernel<<<gg, 256, GM_SMEM>>>(p_ch, p_wdh, bd, p_from, p_res, nullptr);
    ln_kernel<<<FF, 256>>>(p_res, gamma, beta, out);
    (void)in_sizes; (void)n_in; (void)out_size;
}

// round 16
// speedup vs baseline: 1.1359x; 1.0070x over previous
#include <cuda_runtime.h>
#include <cuda_bf16.h>
#include <cstdint>
#include <math.h>

#define HH 16
#define DD 1024
#define DH 64
#define FF 2048
#define TT 2048
#define SS 512

static __constant__ float kLnEps = 1e-5f;
#define SCALE 0.125f  /* 1/sqrt(1024/16) = 1/8 */

// ---------------- scratch (device globals, no allocations) ----------------
__device__ float g_from[FF * DD];
__device__ float g_to[TT * DD];
__device__ float g_q[FF * DD];
__device__ float g_v[TT * DD];
__device__ float g_cb[TT * HH];
__device__ float g_scores[(size_t)HH * FF * TT];   // reused as bf16 probs
__device__ float g_res[FF * DD];
__device__ float g_psum[(size_t)HH * FF * 8];
__device__ float g_rinv[HH * FF];
__device__ __nv_bfloat16 g_qh[(size_t)HH * FF * DD];
__device__ __nv_bfloat16 g_kh[(size_t)TT * DD];
__device__ __nv_bfloat16 g_fh[(size_t)FF * DD];
__device__ __nv_bfloat16 g_th[(size_t)TT * DD];
__device__ __nv_bfloat16 g_ch[(size_t)FF * DD];
__device__ __nv_bfloat16 g_wqh[(size_t)DD * DD];
__device__ __nv_bfloat16 g_wkh[(size_t)DD * DD];
__device__ __nv_bfloat16 g_wvh[(size_t)DD * DD];
__device__ __nv_bfloat16 g_wdh[(size_t)DD * DD];
__device__ __nv_bfloat16 g_vth[(size_t)DD * TT];

// mma.sync m16n8k16 bf16 (portable HMMA; tcgen05 PTX rejected by compute_103)
#define MMA16816(d, a, b0, b1)                                              \
    asm volatile(                                                           \
        "mma.sync.aligned.m16n8k16.row.col.f32.bf16.bf16.f32 "              \
        "{%0,%1,%2,%3}, {%4,%5,%6,%7}, {%8,%9}, {%0,%1,%2,%3};"             \
        : "+f"((d)[0]), "+f"((d)[1]), "+f"((d)[2]), "+f"((d)[3])            \
        : "r"((a)[0]), "r"((a)[1]), "r"((a)[2]), "r"((a)[3]),               \
          "r"(b0), "r"(b1))

__device__ __forceinline__ uint32_t smem_u32(const void* p) {
    uint32_t a;
    asm("{ .reg .u64 t; cvta.to.shared.u64 t, %1; cvt.u32.u64 %0, t; }" : "=r"(a) : "l"(p));
    return a;
}
__device__ __forceinline__ void cp16(uint32_t dst, const void* src) {
    asm volatile("cp.async.cg.shared.global [%0], [%1], 16;" :: "r"(dst), "l"(src));
}
#define CP_COMMIT() asm volatile("cp.async.commit_group;" ::: "memory")
#define CP_WAIT2()  asm volatile("cp.async.wait_group 2;" ::: "memory")
#define CP_WAIT1()  asm volatile("cp.async.wait_group 1;" ::: "memory")
#define CP_WAIT0()  asm volatile("cp.async.wait_group 0;" ::: "memory")

// ---------------- gather (also emits bf16 planes) ----------------
__global__ void gather_kernel(const float* __restrict__ hidden,
                              const int* __restrict__ fpos,
                              const int* __restrict__ tpos) {
    int row = blockIdx.x;
    int fi = fpos[row] & (SS - 1);
    int ti = tpos[row] & (SS - 1);
    const float4* srcf = (const float4*)(hidden + (size_t)fi * DD);
    const float4* srct = (const float4*)(hidden + (size_t)ti * DD);
    float4* dstf = (float4*)(g_from + (size_t)row * DD);
    float4* dstt = (float4*)(g_to + (size_t)row * DD);
    for (int i = threadIdx.x; i < DD / 4; i += blockDim.x) {
        float4 f = srcf[i];
        float4 t = srct[i];
        dstf[i] = f;
        dstt[i] = t;
        size_t o = (size_t)row * DD + i * 4;
        *(__nv_bfloat162*)&g_fh[o]     = __nv_bfloat162(__float2bfloat16(f.x), __float2bfloat16(f.y));
        *(__nv_bfloat162*)&g_fh[o + 2] = __nv_bfloat162(__float2bfloat16(f.z), __float2bfloat16(f.w));
        *(__nv_bfloat162*)&g_th[o]     = __nv_bfloat162(__float2bfloat16(t.x), __float2bfloat16(t.y));
        *(__nv_bfloat162*)&g_th[o + 2] = __nv_bfloat162(__float2bfloat16(t.z), __float2bfloat16(t.w));
    }
}

// ---------------- batched weight transpose ----------------
__global__ void transpose_w4_kernel(const float* __restrict__ w0, const float* __restrict__ w1,
                                    const float* __restrict__ w2, const float* __restrict__ w3,
                                    __nv_bfloat16* __restrict__ o0, __nv_bfloat16* __restrict__ o1,
                                    __nv_bfloat16* __restrict__ o2, __nv_bfloat16* __restrict__ o3) {
    const float* in = (blockIdx.z == 0) ? w0 : (blockIdx.z == 1) ? w1 : (blockIdx.z == 2) ? w2 : w3;
    __nv_bfloat16* oh = (blockIdx.z == 0) ? o0 : (blockIdx.z == 1) ? o1 : (blockIdx.z == 2) ? o2 : o3;
    __shared__ float t[32][33];
    int bc = blockIdx.x * 32, br = blockIdx.y * 32;
    int tx = threadIdx.x, ty = threadIdx.y;   // 32 x 8
#pragma unroll
    for (int j = 0; j < 32; j += 8)
        t[ty + j][tx] = in[(size_t)(br + ty + j) * DD + bc + tx];
    __syncthreads();
#pragma unroll
    for (int j = 0; j < 32; j += 8)
        oh[(size_t)(bc + ty + j) * DD + br + tx] = __float2bfloat16(t[tx][ty + j]);
}

// ---------------- transpose (hi only) ----------------
__global__ void transpose_h_kernel(const float* __restrict__ in, int R, int C,
                                   __nv_bfloat16* __restrict__ oh) {
    __shared__ float t[32][33];
    int bc = blockIdx.x * 32, br = blockIdx.y * 32;
    int tx = threadIdx.x, ty = threadIdx.y;
#pragma unroll
    for (int j = 0; j < 32; j += 8)
        t[ty + j][tx] = in[(size_t)(br + ty + j) * C + bc + tx];
    __syncthreads();
#pragma unroll
    for (int j = 0; j < 32; j += 8)
        oh[(size_t)(bc + ty + j) * R + br + tx] = __float2bfloat16(t[tx][ty + j]);
}

// ---------------- cb ----------------
__global__ void cb_kernel(const float* __restrict__ Wcb, float* __restrict__ cb) {
    int t = blockIdx.x;
    int lane = threadIdx.x & 31, w = threadIdx.x >> 5;
    const float* row = g_to + (size_t)t * DD;
#pragma unroll
    for (int hh = 0; hh < 2; hh++) {
        int h = w * 2 + hh;
        float s = 0.f;
        for (int d = lane; d < DD; d += 32) s += row[d] * Wcb[d * HH + h];
#pragma unroll
        for (int o = 16; o; o >>= 1) s += __shfl_down_sync(0xffffffffu, s, o);
        if (lane == 0) cb[t * HH + h] = s;
    }
}

// ---------------- split mixed-q (bf16) ----------------
__global__ void split_q_kernel(const float* __restrict__ q, const float* __restrict__ mixing,
                               __nv_bfloat16* __restrict__ qh) {
    int h = blockIdx.x >> 11;
    int f = blockIdx.x & (FF - 1);
    int d = threadIdx.x * 4;
    float4 x = *(const float4*)&q[(size_t)f * DD + d];
    float4 m = *(const float4*)&mixing[(size_t)h * DD + d];
    size_t o = ((size_t)h * FF + f) * DD + d;
    *(__nv_bfloat162*)&qh[o]     = __nv_bfloat162(__float2bfloat16(x.x * m.x), __float2bfloat16(x.y * m.y));
    *(__nv_bfloat162*)&qh[o + 2] = __nv_bfloat162(__float2bfloat16(x.z * m.z), __float2bfloat16(x.w * m.w));
}

// ---------------- GEMM core (shared by qkv batched + out GEMM) ----------
#define GM_STAGE 20480
#define GM_SMEM  (4 * GM_STAGE + 128 * 4)

struct GemmOut {
    float* C;
    __nv_bfloat16* Cbf;
    const float* bias;
    const float* addend;
};

__device__ __forceinline__ void gemm_core(
    const __nv_bfloat16* __restrict__ Ah_, const __nv_bfloat16* __restrict__ Bh_,
    const GemmOut& go_, char* gsm, int bm, int bn)
{
    float* sbias = (float*)(gsm + 4 * GM_STAGE);
    uint32_t smb = smem_u32(gsm);
    int tid = threadIdx.x;
    int lane = tid & 31, wid = tid >> 5;
    int wm = (wid & 3) * 32, wn = (wid >> 2) * 64;

    const __nv_bfloat16* Ah = Ah_ + (size_t)bm * DD;
    const __nv_bfloat16* Bh = Bh_ + (size_t)bn * DD;

    if (tid < 128) sbias[tid] = go_.bias ? go_.bias[bn + tid] : 0.f;

    float acc[2][8][4];
#pragma unroll
    for (int mi = 0; mi < 2; mi++)
#pragma unroll
        for (int ni = 0; ni < 8; ni++)
#pragma unroll
            for (int j = 0; j < 4; j++) acc[mi][ni][j] = 0.f;

    int frow = tid >> 1;
    int fc = (tid & 1) * 16;
    uint32_t fb = frow * 80 + (tid & 1) * 32;

    auto issue = [&](int c) {
        int s = c & 3;
        int k0 = c * 32;
        uint32_t sb = smb + s * GM_STAGE;
        size_t go = (size_t)frow * DD + k0 + fc;
        uint32_t d = sb + fb;
        cp16(d, Ah + go);               cp16(d + 16, Ah + go + 8);
        cp16(d + 10240, Bh + go);       cp16(d + 10240 + 16, Bh + go + 8);
        CP_COMMIT();
    };

    issue(0); issue(1);

    for (int c = 0; c < 32; c++) {
        if (c + 2 < 32) issue(c + 2);
        if (c < 30) { CP_WAIT2(); } else if (c == 30) { CP_WAIT1(); } else { CP_WAIT0(); }
        __syncthreads();

        const __nv_bfloat16* pAh = (const __nv_bfloat16*)(gsm + (c & 3) * GM_STAGE);
        const __nv_bfloat16* pBh = pAh + 5120;

#pragma unroll
        for (int ks = 0; ks < 2; ks++) {
            int kk = ks * 16 + 2 * (lane & 3);
            uint32_t ah[2][4];
#pragma unroll
            for (int mi = 0; mi < 2; mi++) {
                int r = wm + mi * 16 + (lane >> 2);
                ah[mi][0] = *(const uint32_t*)&pAh[r * 40 + kk];
                ah[mi][1] = *(const uint32_t*)&pAh[(r + 8) * 40 + kk];
                ah[mi][2] = *(const uint32_t*)&pAh[r * 40 + kk + 8];
                ah[mi][3] = *(const uint32_t*)&pAh[(r + 8) * 40 + kk + 8];
            }
#pragma unroll
            for (int ni = 0; ni < 8; ni++) {
                int n = wn + ni * 8 + (lane >> 2);
                uint32_t bh0 = *(const uint32_t*)&pBh[n * 40 + kk];
                uint32_t bh1 = *(const uint32_t*)&pBh[n * 40 + kk + 8];
#pragma unroll
                for (int mi = 0; mi < 2; mi++)
                    MMA16816(acc[mi][ni], ah[mi], bh0, bh1);
            }
        }
    }

    if (go_.Cbf) {
        __nv_bfloat16* ob = go_.Cbf + (size_t)bm * DD + bn;
#pragma unroll
        for (int mi = 0; mi < 2; mi++) {
            int r = wm + mi * 16 + (lane >> 2);
#pragma unroll
            for (int ni = 0; ni < 8; ni++) {
                int tcol = wn + ni * 8 + 2 * (lane & 3);
                float b0 = sbias[tcol], b1 = sbias[tcol + 1];
                __nv_bfloat162 v0 = __nv_bfloat162(__float2bfloat16(acc[mi][ni][0] + b0),
                                                   __float2bfloat16(acc[mi][ni][1] + b1));
                __nv_bfloat162 v1 = __nv_bfloat162(__float2bfloat16(acc[mi][ni][2] + b0),
                                                   __float2bfloat16(acc[mi][ni][3] + b1));
                *(__nv_bfloat162*)&ob[(size_t)r * DD + tcol] = v0;
                *(__nv_bfloat162*)&ob[(size_t)(r + 8) * DD + tcol] = v1;
            }
        }
    } else {
        float* outp = go_.C + (size_t)bm * DD + bn;
        const float* add = go_.addend ? go_.addend + (size_t)bm * DD + bn : nullptr;
#pragma unroll
        for (int mi = 0; mi < 2; mi++) {
            int r = wm + mi * 16 + (lane >> 2);
#pragma unroll
            for (int ni = 0; ni < 8; ni++) {
                int tcol = wn + ni * 8 + 2 * (lane & 3);
                float b0 = sbias[tcol], b1 = sbias[tcol + 1];
                float2 v0 = make_float2(acc[mi][ni][0] + b0, acc[mi][ni][1] + b1);
                float2 v1 = make_float2(acc[mi][ni][2] + b0, acc[mi][ni][3] + b1);
                if (add) {
                    float2 a0 = *(const float2*)&add[(size_t)r * DD + tcol];
                    float2 a1 = *(const float2*)&add[(size_t)(r + 8) * DD + tcol];
                    v0.x += a0.x; v0.y += a0.y;
                    v1.x += a1.x; v1.y += a1.y;
                }
                *(float2*)&outp[(size_t)r * DD + tcol] = v0;
                *(float2*)&outp[(size_t)(r + 8) * DD + tcol] = v1;
            }
        }
    }
}

// batched q/k/v: z=0 q(fp32), z=1 k(bf16), z=2 v(fp32+bias)
__global__ __launch_bounds__(256, 2) void qkv_kernel(
    const __nv_bfloat16* __restrict__ fh, const __nv_bfloat16* __restrict__ th,
    const __nv_bfloat16* __restrict__ wq, const __nv_bfloat16* __restrict__ wk,
    const __nv_bfloat16* __restrict__ wv,
    const float* __restrict__ bv,
    float* __restrict__ q, __nv_bfloat16* __restrict__ kh, float* __restrict__ v)
{
    extern __shared__ char gsm[];
    int z = blockIdx.z;
    const __nv_bfloat16* A = (z == 0) ? fh : th;
    const __nv_bfloat16* B = (z == 0) ? wq : (z == 1) ? wk : wv;
    GemmOut go;
    go.C = (z == 0) ? q : v;
    go.Cbf = (z == 1) ? kh : nullptr;
    go.bias = (z == 2) ? bv : nullptr;
    go.addend = nullptr;
    gemm_core(A, B, go, gsm, blockIdx.y * 128, blockIdx.x * 128);
}

// out GEMM: ctx_bf16 @ wd + bd + from
__global__ __launch_bounds__(256, 2) void outgemm_kernel(
    const __nv_bfloat16* __restrict__ ch, const __nv_bfloat16* __restrict__ wd,
    const float* __restrict__ bd, const float* __restrict__ fromp,
    float* __restrict__ res)
{
    extern __shared__ char gsm[];
    GemmOut go;
    go.C = res;
    go.Cbf = nullptr;
    go.bias = bd;
    go.addend = fromp;
    gemm_core(ch, wd, go, gsm, blockIdx.y * 128, blockIdx.x * 128);
}

// ---------------- scores: single-product bf16, 4-stage, one sync/chunk ---
#define SC_STAGE 30720
#define SC_SMEM  (4 * SC_STAGE + 1024 + 2048)

__global__ __launch_bounds__(256) void scores_db_kernel(
    const __nv_bfloat16* __restrict__ qh,
    const __nv_bfloat16* __restrict__ kh,
    const float* __restrict__ cb, __nv_bfloat16* __restrict__ probs,
    float* __restrict__ psum)
{
    extern __shared__ char ssm[];
    float* scb = (float*)(ssm + 4 * SC_STAGE);
    float* sRow = (float*)(ssm + 4 * SC_STAGE + 1024);   // [128][4]
    uint32_t smb = smem_u32(ssm);

    int tid = threadIdx.x;
    int lane = tid & 31, wid = tid >> 5;
    int h = blockIdx.z, bm = blockIdx.y * 128, bn = blockIdx.x * 256;
    int wm = (wid & 1) * 64, wn = (wid >> 1) * 64;

    const __nv_bfloat16* Ah = qh + ((size_t)h * FF + bm) * DD;
    const __nv_bfloat16* Bh = kh + (size_t)bn * DD;

    scb[tid] = cb[(size_t)(bn + tid) * HH + h];

    float acc[4][8][4];
#pragma unroll
    for (int mi = 0; mi < 4; mi++)
#pragma unroll
        for (int ni = 0; ni < 8; ni++)
#pragma unroll
            for (int j = 0; j < 4; j++) acc[mi][ni][j] = 0.f;

    int ar = tid >> 2, ac = tid & 3;

    auto issue = [&](int c) {
        int s = c & 3;
        int k0 = c * 32;
        uint32_t sb = smb + s * SC_STAGE;
#pragma unroll
        for (int i = 0; i < 2; i++) {
            int row = ar + i * 64;
            cp16(sb + row * 80 + ac * 16, Ah + (size_t)row * DD + k0 + ac * 8);
        }
#pragma unroll
        for (int i = 0; i < 4; i++) {
            int row = ar + i * 64;
            cp16(sb + 10240 + row * 80 + ac * 16, Bh + (size_t)row * DD + k0 + ac * 8);
        }
        CP_COMMIT();
    };

    issue(0); issue(1);

    for (int c = 0; c < 32; c++) {
        if (c + 2 < 32) issue(c + 2);
        if (c < 30) { CP_WAIT2(); } else if (c == 30) { CP_WAIT1(); } else { CP_WAIT0(); }
        __syncthreads();

        const __nv_bfloat16* pAh = (const __nv_bfloat16*)(ssm + (c & 3) * SC_STAGE);
        const __nv_bfloat16* pBh = pAh + 5120;

#pragma unroll
        for (int ks = 0; ks < 2; ks++) {
            int kk = ks * 16 + 2 * (lane & 3);
            uint32_t ah[4][4];
#pragma unroll
            for (int mi = 0; mi < 4; mi++) {
                int r = wm + mi * 16 + (lane >> 2);
                ah[mi][0] = *(const uint32_t*)&pAh[r * 40 + kk];
                ah[mi][1] = *(const uint32_t*)&pAh[(r + 8) * 40 + kk];
                ah[mi][2] = *(const uint32_t*)&pAh[r * 40 + kk + 8];
                ah[mi][3] = *(const uint32_t*)&pAh[(r + 8) * 40 + kk + 8];
            }
#pragma unroll
            for (int ni = 0; ni < 8; ni++) {
                int n = wn + ni * 8 + (lane >> 2);
                uint32_t bh0 = *(const uint32_t*)&pBh[n * 40 + kk];
                uint32_t bh1 = *(const uint32_t*)&pBh[n * 40 + kk + 8];
#pragma unroll
                for (int mi = 0; mi < 4; mi++)
                    MMA16816(acc[mi][ni], ah[mi], bh0, bh1);
            }
        }
    }

    // epilogue: exp(logit) -> bf16 probs, per-row partial sums (deterministic)
    __nv_bfloat16* out = probs + ((size_t)h * FF + bm) * TT + bn;
    float rs[4][2];
#pragma unroll
    for (int mi = 0; mi < 4; mi++) { rs[mi][0] = 0.f; rs[mi][1] = 0.f; }
#pragma unroll
    for (int mi = 0; mi < 4; mi++) {
        int frow = wm + mi * 16 + (lane >> 2);
#pragma unroll
        for (int ni = 0; ni < 8; ni++) {
            int tcol = wn + ni * 8 + 2 * (lane & 3);
            float cb0 = scb[tcol], cb1 = scb[tcol + 1];
            float e0 = __expf((acc[mi][ni][0] + cb0) * SCALE);
            float e1 = __expf((acc[mi][ni][1] + cb1) * SCALE);
            float e2 = __expf((acc[mi][ni][2] + cb0) * SCALE);
            float e3 = __expf((acc[mi][ni][3] + cb1) * SCALE);
            rs[mi][0] += e0 + e1;
            rs[mi][1] += e2 + e3;
            __nv_bfloat162 p0 = __nv_bfloat162(__float2bfloat16(e0), __float2bfloat16(e1));
            __nv_bfloat162 p1 = __nv_bfloat162(__float2bfloat16(e2), __float2bfloat16(e3));
            *(__nv_bfloat162*)&out[(size_t)frow * TT + tcol] = p0;
            *(__nv_bfloat162*)&out[(size_t)(frow + 8) * TT + tcol] = p1;
        }
    }
#pragma unroll
    for (int mi = 0; mi < 4; mi++)
#pragma unroll
        for (int rr = 0; rr < 2; rr++) {
            rs[mi][rr] += __shfl_xor_sync(0xffffffffu, rs[mi][rr], 1);
            rs[mi][rr] += __shfl_xor_sync(0xffffffffu, rs[mi][rr], 2);
        }
    int wnidx = wid >> 1;
    __syncthreads();
    if ((lane & 3) == 0) {
#pragma unroll
        for (int mi = 0; mi < 4; mi++) {
            int r0 = wm + mi * 16 + (lane >> 2);
            sRow[r0 * 4 + wnidx] = rs[mi][0];
            sRow[(r0 + 8) * 4 + wnidx] = rs[mi][1];
        }
    }
    __syncthreads();
    if (tid < 128) {
        float s = sRow[tid * 4 + 0] + sRow[tid * 4 + 1]
                + sRow[tid * 4 + 2] + sRow[tid * 4 + 3];
        psum[((size_t)h * FF + bm + tid) * 8 + blockIdx.x] = s;
    }
}

// ---------------- rinv ----------------
__global__ void rinv_kernel(const float* __restrict__ psum, float* __restrict__ rinv) {
    int i = blockIdx.x * 256 + threadIdx.x;
    float s = 0.f;
#pragma unroll
    for (int j = 0; j < 8; j++) s += psum[(size_t)i * 8 + j];
    rinv[i] = 1.0f / s;
}

// ---------------- ctx: bf16 probs @ vT -> bf16, 2-stage, 2 CTAs/SM -------
#define CT_AST 72
#define CT_ASZ (128 * 72 * 2)
#define CT_VSZ (64 * 72 * 2)
#define CT_STAGE (CT_ASZ + CT_VSZ)
#define CT_SMEM (2 * CT_STAGE)

__global__ __launch_bounds__(256, 2) void ctx_db_kernel(
    const __nv_bfloat16* __restrict__ probs, const float* __restrict__ rinv,
    const __nv_bfloat16* __restrict__ vth, __nv_bfloat16* __restrict__ ctxb)
{
    extern __shared__ char csm[];
    uint32_t smb = smem_u32(csm);
    int tid = threadIdx.x;
    int lane = tid & 31, wid = tid >> 5;
    int h = blockIdx.y, bm = blockIdx.x * 128;
    int wm = (wid & 3) * 32, wn = (wid >> 2) * 32;

    const __nv_bfloat16* P = probs + ((size_t)h * FF + bm) * TT;
    const __nv_bfloat16* V = vth + (size_t)h * DH * TT;

    float acc[2][4][4];
#pragma unroll
    for (int mi = 0; mi < 2; mi++)
#pragma unroll
        for (int ni = 0; ni < 4; ni++)
#pragma unroll
            for (int j = 0; j < 4; j++) acc[mi][ni][j] = 0.f;

    int arow = tid >> 3, ac = tid & 7;

    auto issue = [&](int c, int s) {
        int k0 = c * 64;
        uint32_t sb = smb + s * CT_STAGE;
#pragma unroll
        for (int i = 0; i < 4; i++) {
            int row = arow + i * 32;
            cp16(sb + row * 144 + ac * 16, P + (size_t)row * TT + k0 + ac * 8);
        }
#pragma unroll
        for (int i = 0; i < 2; i++) {
            int row = arow + i * 32;
            cp16(sb + CT_ASZ + row * 144 + ac * 16, V + (size_t)row * TT + k0 + ac * 8);
        }
        CP_COMMIT();
    };

    issue(0, 0);

    for (int c = 0; c < 32; c++) {
        int s = c & 1;
        if (c < 31) issue(c + 1, s ^ 1);
        if (c < 31) { CP_WAIT1(); } else { CP_WAIT0(); }
        __syncthreads();

        const __nv_bfloat16* pA = (const __nv_bfloat16*)(csm + s * CT_STAGE);
        const __nv_bfloat16* pV = (const __nv_bfloat16*)(csm + s * CT_STAGE + CT_ASZ);

#pragma unroll
        for (int ks = 0; ks < 4; ks++) {
            int kk = ks * 16 + 2 * (lane & 3);
            uint32_t a[2][4];
#pragma unroll
            for (int mi = 0; mi < 2; mi++) {
                int r = wm + mi * 16 + (lane >> 2);
                a[mi][0] = *(const uint32_t*)&pA[r * CT_AST + kk];
                a[mi][1] = *(const uint32_t*)&pA[(r + 8) * CT_AST + kk];
                a[mi][2] = *(const uint32_t*)&pA[r * CT_AST + kk + 8];
                a[mi][3] = *(const uint32_t*)&pA[(r + 8) * CT_AST + kk + 8];
            }
#pragma unroll
            for (int ni = 0; ni < 4; ni++) {
                int n = wn + ni * 8 + (lane >> 2);
                uint32_t b0 = *(const uint32_t*)&pV[n * CT_AST + kk];
                uint32_t b1 = *(const uint32_t*)&pV[n * CT_AST + kk + 8];
#pragma unroll
                for (int mi = 0; mi < 2; mi++)
                    MMA16816(acc[mi][ni], a[mi], b0, b1);
            }
        }
        __syncthreads();
    }

    const float* rv = rinv + (size_t)h * FF + bm;
    __nv_bfloat16* outp = ctxb + (size_t)bm * DD + h * DH;
#pragma unroll
    for (int mi = 0; mi < 2; mi++) {
        int frow = wm + mi * 16 + (lane >> 2);
        float r0 = rv[frow], r1 = rv[frow + 8];
#pragma unroll
        for (int ni = 0; ni < 4; ni++) {
            int tcol = wn + ni * 8 + 2 * (lane & 3);
            __nv_bfloat162 v0 = __nv_bfloat162(__float2bfloat16(acc[mi][ni][0] * r0),
                                               __float2bfloat16(acc[mi][ni][1] * r0));
            __nv_bfloat162 v1 = __nv_bfloat162(__float2bfloat16(acc[mi][ni][2] * r1),
                                               __float2bfloat16(acc[mi][ni][3] * r1));
            *(__nv_bfloat162*)&outp[(size_t)frow * DD + tcol] = v0;
            *(__nv_bfloat162*)&outp[(size_t)(frow + 8) * DD + tcol] = v1;
        }
    }
}

// ---------------- LayerNorm ----------------
__global__ void ln_kernel(const float* __restrict__ res,
                          const float* __restrict__ gamma,
                          const float* __restrict__ beta,
                          float* __restrict__ out) {
    int r = blockIdx.x;
    const float* row = res + (size_t)r * DD;
    float* orow = out + (size_t)r * DD;
    __shared__ float red[256];
    int tid = threadIdx.x;
    float4 x = *(const float4*)&row[tid * 4];
    float s = x.x + x.y + x.z + x.w;
    red[tid] = s;
    __syncthreads();
    for (int st = 128; st; st >>= 1) {
        if (tid < st) red[tid] += red[tid + st];
        __syncthreads();
    }
    float mean = red[0] * (1.0f / DD);
    __syncthreads();
    float dx = x.x - mean, dy = x.y - mean, dz = x.z - mean, dw = x.w - mean;
    red[tid] = dx * dx + dy * dy + dz * dz + dw * dw;
    __syncthreads();
    for (int st = 128; st; st >>= 1) {
        if (tid < st) red[tid] += red[tid + st];
        __syncthreads();
    }
    float var = red[0] * (1.0f / DD);
    float rstd = rsqrtf(var + kLnEps);
    float4 g = *(const float4*)&gamma[tid * 4];
    float4 b = *(const float4*)&beta[tid * 4];
    float4 o;
    o.x = dx * rstd * g.x + b.x;
    o.y = dy * rstd * g.y + b.y;
    o.z = dz * rstd * g.z + b.z;
    o.w = dw * rstd * g.w + b.w;
    *(float4*)&orow[tid * 4] = o;
}

// ---------------- launch ----------------
extern "C" void kernel_launch(void* const* d_in, const int* in_sizes, int n_in,
                              void* d_out, int out_size) {
    const float* hidden = (const float*)d_in[0];
    const int* fpos = (const int*)d_in[1];
    const int* tpos = (const int*)d_in[2];
    const float* Wq = (const float*)d_in[3];
    const float* Wk = (const float*)d_in[4];
    const float* Wcb = (const float*)d_in[5];
    const float* Wv = (const float*)d_in[6];
    const float* bv = (const float*)d_in[7];
    const float* mixing = (const float*)d_in[8];
    const float* Wd = (const float*)d_in[9];
    const float* bd = (const float*)d_in[10];
    const float* gamma = (const float*)d_in[11];
    const float* beta = (const float*)d_in[12];
    float* out = (float*)d_out;

    float *p_from, *p_to, *p_q, *p_v, *p_cb, *p_scores, *p_res;
    float *p_psum, *p_rinv;
    __nv_bfloat16 *p_qh, *p_kh;
    __nv_bfloat16 *p_fh, *p_th, *p_ch;
    __nv_bfloat16 *p_wqh, *p_wkh, *p_wvh, *p_wdh, *p_vth;
    cudaGetSymbolAddress((void**)&p_from, g_from);
    cudaGetSymbolAddress((void**)&p_to, g_to);
    cudaGetSymbolAddress((void**)&p_q, g_q);
    cudaGetSymbolAddress((void**)&p_v, g_v);
    cudaGetSymbolAddress((void**)&p_cb, g_cb);
    cudaGetSymbolAddress((void**)&p_scores, g_scores);
    cudaGetSymbolAddress((void**)&p_res, g_res);
    cudaGetSymbolAddress((void**)&p_psum, g_psum);
    cudaGetSymbolAddress((void**)&p_rinv, g_rinv);
    cudaGetSymbolAddress((void**)&p_qh, g_qh);
    cudaGetSymbolAddress((void**)&p_kh, g_kh);
    cudaGetSymbolAddress((void**)&p_fh, g_fh);
    cudaGetSymbolAddress((void**)&p_th, g_th);
    cudaGetSymbolAddress((void**)&p_ch, g_ch);
    cudaGetSymbolAddress((void**)&p_wqh, g_wqh);
    cudaGetSymbolAddress((void**)&p_wkh, g_wkh);
    cudaGetSymbolAddress((void**)&p_wvh, g_wvh);
    cudaGetSymbolAddress((void**)&p_wdh, g_wdh);
    cudaGetSymbolAddress((void**)&p_vth, g_vth);

    __nv_bfloat16* p_probs = (__nv_bfloat16*)p_scores;

    cudaFuncSetAttribute(scores_db_kernel,
                         cudaFuncAttributeMaxDynamicSharedMemorySize, SC_SMEM);
    cudaFuncSetAttribute(qkv_kernel,
                         cudaFuncAttributeMaxDynamicSharedMemorySize, GM_SMEM);
    cudaFuncSetAttribute(outgemm_kernel,
                         cudaFuncAttributeMaxDynamicSharedMemorySize, GM_SMEM);
    cudaFuncSetAttribute(ctx_db_kernel,
                         cudaFuncAttributeMaxDynamicSharedMemorySize, CT_SMEM);

    dim3 tb(32, 8);

    gather_kernel<<<FF, 256>>>(hidden, fpos, tpos);
    transpose_w4_kernel<<<dim3(DD / 32, DD / 32, 4), tb>>>(
        Wq, Wk, Wv, Wd, p_wqh, p_wkh, p_wvh, p_wdh);

    qkv_kernel<<<dim3(DD / 128, FF / 128, 3), 256, GM_SMEM>>>(
        p_fh, p_th, p_wqh, p_wkh, p_wvh, bv, p_q, p_kh, p_v);
    cb_kernel<<<TT, 256>>>(Wcb, p_cb);

    split_q_kernel<<<HH * FF, 256>>>(p_q, mixing, p_qh);
    transpose_h_kernel<<<dim3(DD / 32, TT / 32), tb>>>(p_v, TT, DD, p_vth);

    scores_db_kernel<<<dim3(TT / 256, FF / 128, HH), 256, SC_SMEM>>>(
        p_qh, p_kh, p_cb, p_probs, p_psum);

    rinv_kernel<<<HH * FF / 256, 256>>>(p_psum, p_rinv);
    ctx_db_kernel<<<dim3(FF / 128, HH), 256, CT_SMEM>>>(p_probs, p_rinv, p_vth, p_ch);

    outgemm_kernel<<<dim3(DD / 128, FF / 128), 256, GM_SMEM>>>(
        p_ch, p_wdh, bd, p_from, p_res);
    ln_kernel<<<FF, 256>>>(p_res, gamma, beta, out);
    (void)in_sizes; (void)n_in; (void)out_size;
}

// round 17
// speedup vs baseline: 1.1862x; 1.0443x over previous
#include <cuda_runtime.h>
#include <cuda_bf16.h>
#include <cstdint>
#include <math.h>

#define HH 16
#define DD 1024
#define DH 64
#define FF 2048
#define TT 2048
#define SS 512

static __constant__ float kLnEps = 1e-5f;
#define SCALE 0.125f  /* 1/sqrt(1024/16) = 1/8 */

// ---------------- scratch (device globals, no allocations) ----------------
__device__ float g_from[FF * DD];
__device__ float g_to[TT * DD];
__device__ float g_v[TT * DD];
__device__ float g_cb[TT * HH];
__device__ float g_scores[(size_t)HH * FF * TT];   // reused as bf16 probs
__device__ float g_res[FF * DD];
__device__ float g_psum[(size_t)HH * FF * 8];
__device__ float g_rinv[HH * FF];
__device__ __nv_bfloat16 g_qh[(size_t)FF * DD];    // bf16 q (pre-mixing)
__device__ __nv_bfloat16 g_kh[(size_t)TT * DD];
__device__ __nv_bfloat16 g_fh[(size_t)FF * DD];
__device__ __nv_bfloat16 g_th[(size_t)TT * DD];
__device__ __nv_bfloat16 g_ch[(size_t)FF * DD];
__device__ __nv_bfloat16 g_wqh[(size_t)DD * DD];
__device__ __nv_bfloat16 g_wkh[(size_t)DD * DD];
__device__ __nv_bfloat16 g_wvh[(size_t)DD * DD];
__device__ __nv_bfloat16 g_wdh[(size_t)DD * DD];
__device__ __nv_bfloat16 g_vth[(size_t)DD * TT];

// mma.sync m16n8k16 bf16 (portable HMMA; tcgen05 PTX rejected by compute_103)
#define MMA16816(d, a, b0, b1)                                              \
    asm volatile(                                                           \
        "mma.sync.aligned.m16n8k16.row.col.f32.bf16.bf16.f32 "              \
        "{%0,%1,%2,%3}, {%4,%5,%6,%7}, {%8,%9}, {%0,%1,%2,%3};"             \
        : "+f"((d)[0]), "+f"((d)[1]), "+f"((d)[2]), "+f"((d)[3])            \
        : "r"((a)[0]), "r"((a)[1]), "r"((a)[2]), "r"((a)[3]),               \
          "r"(b0), "r"(b1))

#define MULBF2(dst, a, b) \
    asm("mul.bf16x2 %0, %1, %2;" : "=r"(dst) : "r"(a), "r"(b))

__device__ __forceinline__ uint32_t smem_u32(const void* p) {
    uint32_t a;
    asm("{ .reg .u64 t; cvta.to.shared.u64 t, %1; cvt.u32.u64 %0, t; }" : "=r"(a) : "l"(p));
    return a;
}
__device__ __forceinline__ void cp16(uint32_t dst, const void* src) {
    asm volatile("cp.async.cg.shared.global [%0], [%1], 16;" :: "r"(dst), "l"(src));
}
#define CP_COMMIT() asm volatile("cp.async.commit_group;" ::: "memory")
#define CP_WAIT2()  asm volatile("cp.async.wait_group 2;" ::: "memory")
#define CP_WAIT1()  asm volatile("cp.async.wait_group 1;" ::: "memory")
#define CP_WAIT0()  asm volatile("cp.async.wait_group 0;" ::: "memory")

// ---------------- gather (also emits bf16 planes) ----------------
__global__ void gather_kernel(const float* __restrict__ hidden,
                              const int* __restrict__ fpos,
                              const int* __restrict__ tpos) {
    int row = blockIdx.x;
    int fi = fpos[row] & (SS - 1);
    int ti = tpos[row] & (SS - 1);
    const float4* srcf = (const float4*)(hidden + (size_t)fi * DD);
    const float4* srct = (const float4*)(hidden + (size_t)ti * DD);
    float4* dstf = (float4*)(g_from + (size_t)row * DD);
    float4* dstt = (float4*)(g_to + (size_t)row * DD);
    for (int i = threadIdx.x; i < DD / 4; i += blockDim.x) {
        float4 f = srcf[i];
        float4 t = srct[i];
        dstf[i] = f;
        dstt[i] = t;
        size_t o = (size_t)row * DD + i * 4;
        *(__nv_bfloat162*)&g_fh[o]     = __nv_bfloat162(__float2bfloat16(f.x), __float2bfloat16(f.y));
        *(__nv_bfloat162*)&g_fh[o + 2] = __nv_bfloat162(__float2bfloat16(f.z), __float2bfloat16(f.w));
        *(__nv_bfloat162*)&g_th[o]     = __nv_bfloat162(__float2bfloat16(t.x), __float2bfloat16(t.y));
        *(__nv_bfloat162*)&g_th[o + 2] = __nv_bfloat162(__float2bfloat16(t.z), __float2bfloat16(t.w));
    }
}

// ---------------- batched weight transpose ----------------
__global__ void transpose_w4_kernel(const float* __restrict__ w0, const float* __restrict__ w1,
                                    const float* __restrict__ w2, const float* __restrict__ w3,
                                    __nv_bfloat16* __restrict__ o0, __nv_bfloat16* __restrict__ o1,
                                    __nv_bfloat16* __restrict__ o2, __nv_bfloat16* __restrict__ o3) {
    const float* in = (blockIdx.z == 0) ? w0 : (blockIdx.z == 1) ? w1 : (blockIdx.z == 2) ? w2 : w3;
    __nv_bfloat16* oh = (blockIdx.z == 0) ? o0 : (blockIdx.z == 1) ? o1 : (blockIdx.z == 2) ? o2 : o3;
    __shared__ float t[32][33];
    int bc = blockIdx.x * 32, br = blockIdx.y * 32;
    int tx = threadIdx.x, ty = threadIdx.y;   // 32 x 8
#pragma unroll
    for (int j = 0; j < 32; j += 8)
        t[ty + j][tx] = in[(size_t)(br + ty + j) * DD + bc + tx];
    __syncthreads();
#pragma unroll
    for (int j = 0; j < 32; j += 8)
        oh[(size_t)(bc + ty + j) * DD + br + tx] = __float2bfloat16(t[tx][ty + j]);
}

// ---------------- transpose (hi only) ----------------
__global__ void transpose_h_kernel(const float* __restrict__ in, int R, int C,
                                   __nv_bfloat16* __restrict__ oh) {
    __shared__ float t[32][33];
    int bc = blockIdx.x * 32, br = blockIdx.y * 32;
    int tx = threadIdx.x, ty = threadIdx.y;
#pragma unroll
    for (int j = 0; j < 32; j += 8)
        t[ty + j][tx] = in[(size_t)(br + ty + j) * C + bc + tx];
    __syncthreads();
#pragma unroll
    for (int j = 0; j < 32; j += 8)
        oh[(size_t)(bc + ty + j) * R + br + tx] = __float2bfloat16(t[tx][ty + j]);
}

// ---------------- cb: smem-staged Wcb, conflict-free (17-pad) ------------
#define CB_SMEM (DD * 17 * 4)

__global__ __launch_bounds__(256) void cb_kernel(const float* __restrict__ Wcb,
                                                 float* __restrict__ cb) {
    extern __shared__ float sW[];   // [1024][17]
    int tid = threadIdx.x;
    for (int i = tid; i < DD * HH; i += 256) {
        int d = i >> 4, h = i & 15;
        sW[d * 17 + h] = Wcb[i];
    }
    __syncthreads();
    int lane = tid & 31, w = tid >> 5;
    int t = blockIdx.x * 8 + w;
    const float* row = g_to + (size_t)t * DD;
    float acc[16];
#pragma unroll
    for (int h = 0; h < 16; h++) acc[h] = 0.f;
    for (int i = 0; i < 32; i++) {
        int d = i * 32 + lane;
        float rv = row[d];
        const float* wp = &sW[d * 17];
#pragma unroll
        for (int h = 0; h < 16; h++) acc[h] += rv * wp[h];
    }
#pragma unroll
    for (int h = 0; h < 16; h++) {
        float s = acc[h];
#pragma unroll
        for (int o = 16; o; o >>= 1) s += __shfl_down_sync(0xffffffffu, s, o);
        if (lane == 0) cb[t * HH + h] = s;
    }
}

// ---------------- GEMM core (shared by qkv batched + out GEMM) ----------
#define GM_STAGE 20480
#define GM_SMEM  (4 * GM_STAGE + 128 * 4)

struct GemmOut {
    float* C;
    __nv_bfloat16* Cbf;
    const float* bias;
    const float* addend;
};

__device__ __forceinline__ void gemm_core(
    const __nv_bfloat16* __restrict__ Ah_, const __nv_bfloat16* __restrict__ Bh_,
    const GemmOut& go_, char* gsm, int bm, int bn)
{
    float* sbias = (float*)(gsm + 4 * GM_STAGE);
    uint32_t smb = smem_u32(gsm);
    int tid = threadIdx.x;
    int lane = tid & 31, wid = tid >> 5;
    int wm = (wid & 3) * 32, wn = (wid >> 2) * 64;

    const __nv_bfloat16* Ah = Ah_ + (size_t)bm * DD;
    const __nv_bfloat16* Bh = Bh_ + (size_t)bn * DD;

    if (tid < 128) sbias[tid] = go_.bias ? go_.bias[bn + tid] : 0.f;

    float acc[2][8][4];
#pragma unroll
    for (int mi = 0; mi < 2; mi++)
#pragma unroll
        for (int ni = 0; ni < 8; ni++)
#pragma unroll
            for (int j = 0; j < 4; j++) acc[mi][ni][j] = 0.f;

    int frow = tid >> 1;
    int fc = (tid & 1) * 16;
    uint32_t fb = frow * 80 + (tid & 1) * 32;

    auto issue = [&](int c) {
        int s = c & 3;
        int k0 = c * 32;
        uint32_t sb = smb + s * GM_STAGE;
        size_t go = (size_t)frow * DD + k0 + fc;
        uint32_t d = sb + fb;
        cp16(d, Ah + go);               cp16(d + 16, Ah + go + 8);
        cp16(d + 10240, Bh + go);       cp16(d + 10240 + 16, Bh + go + 8);
        CP_COMMIT();
    };

    issue(0); issue(1);

    for (int c = 0; c < 32; c++) {
        if (c + 2 < 32) issue(c + 2);
        if (c < 30) { CP_WAIT2(); } else if (c == 30) { CP_WAIT1(); } else { CP_WAIT0(); }
        __syncthreads();

        const __nv_bfloat16* pAh = (const __nv_bfloat16*)(gsm + (c & 3) * GM_STAGE);
        const __nv_bfloat16* pBh = pAh + 5120;

#pragma unroll
        for (int ks = 0; ks < 2; ks++) {
            int kk = ks * 16 + 2 * (lane & 3);
            uint32_t ah[2][4];
#pragma unroll
            for (int mi = 0; mi < 2; mi++) {
                int r = wm + mi * 16 + (lane >> 2);
                ah[mi][0] = *(const uint32_t*)&pAh[r * 40 + kk];
                ah[mi][1] = *(const uint32_t*)&pAh[(r + 8) * 40 + kk];
                ah[mi][2] = *(const uint32_t*)&pAh[r * 40 + kk + 8];
                ah[mi][3] = *(const uint32_t*)&pAh[(r + 8) * 40 + kk + 8];
            }
#pragma unroll
            for (int ni = 0; ni < 8; ni++) {
                int n = wn + ni * 8 + (lane >> 2);
                uint32_t bh0 = *(const uint32_t*)&pBh[n * 40 + kk];
                uint32_t bh1 = *(const uint32_t*)&pBh[n * 40 + kk + 8];
#pragma unroll
                for (int mi = 0; mi < 2; mi++)
                    MMA16816(acc[mi][ni], ah[mi], bh0, bh1);
            }
        }
    }

    if (go_.Cbf) {
        __nv_bfloat16* ob = go_.Cbf + (size_t)bm * DD + bn;
#pragma unroll
        for (int mi = 0; mi < 2; mi++) {
            int r = wm + mi * 16 + (lane >> 2);
#pragma unroll
            for (int ni = 0; ni < 8; ni++) {
                int tcol = wn + ni * 8 + 2 * (lane & 3);
                float b0 = sbias[tcol], b1 = sbias[tcol + 1];
                __nv_bfloat162 v0 = __nv_bfloat162(__float2bfloat16(acc[mi][ni][0] + b0),
                                                   __float2bfloat16(acc[mi][ni][1] + b1));
                __nv_bfloat162 v1 = __nv_bfloat162(__float2bfloat16(acc[mi][ni][2] + b0),
                                                   __float2bfloat16(acc[mi][ni][3] + b1));
                *(__nv_bfloat162*)&ob[(size_t)r * DD + tcol] = v0;
                *(__nv_bfloat162*)&ob[(size_t)(r + 8) * DD + tcol] = v1;
            }
        }
    } else {
        float* outp = go_.C + (size_t)bm * DD + bn;
        const float* add = go_.addend ? go_.addend + (size_t)bm * DD + bn : nullptr;
#pragma unroll
        for (int mi = 0; mi < 2; mi++) {
            int r = wm + mi * 16 + (lane >> 2);
#pragma unroll
            for (int ni = 0; ni < 8; ni++) {
                int tcol = wn + ni * 8 + 2 * (lane & 3);
                float b0 = sbias[tcol], b1 = sbias[tcol + 1];
                float2 v0 = make_float2(acc[mi][ni][0] + b0, acc[mi][ni][1] + b1);
                float2 v1 = make_float2(acc[mi][ni][2] + b0, acc[mi][ni][3] + b1);
                if (add) {
                    float2 a0 = *(const float2*)&add[(size_t)r * DD + tcol];
                    float2 a1 = *(const float2*)&add[(size_t)(r + 8) * DD + tcol];
                    v0.x += a0.x; v0.y += a0.y;
                    v1.x += a1.x; v1.y += a1.y;
                }
                *(float2*)&outp[(size_t)r * DD + tcol] = v0;
                *(float2*)&outp[(size_t)(r + 8) * DD + tcol] = v1;
            }
        }
    }
}

// batched q/k/v: z=0 q(bf16), z=1 k(bf16), z=2 v(fp32+bias)
__global__ __launch_bounds__(256, 2) void qkv_kernel(
    const __nv_bfloat16* __restrict__ fh, const __nv_bfloat16* __restrict__ th,
    const __nv_bfloat16* __restrict__ wq, const __nv_bfloat16* __restrict__ wk,
    const __nv_bfloat16* __restrict__ wv,
    const float* __restrict__ bv,
    __nv_bfloat16* __restrict__ qh, __nv_bfloat16* __restrict__ kh,
    float* __restrict__ v)
{
    extern __shared__ char gsm[];
    int z = blockIdx.z;
    const __nv_bfloat16* A = (z == 0) ? fh : th;
    const __nv_bfloat16* B = (z == 0) ? wq : (z == 1) ? wk : wv;
    GemmOut go;
    go.C = (z == 2) ? v : nullptr;
    go.Cbf = (z == 0) ? qh : (z == 1) ? kh : nullptr;
    go.bias = (z == 2) ? bv : nullptr;
    go.addend = nullptr;
    gemm_core(A, B, go, gsm, blockIdx.y * 128, blockIdx.x * 128);
}

// out GEMM: ctx_bf16 @ wd + bd + from
__global__ __launch_bounds__(256, 2) void outgemm_kernel(
    const __nv_bfloat16* __restrict__ ch, const __nv_bfloat16* __restrict__ wd,
    const float* __restrict__ bd, const float* __restrict__ fromp,
    float* __restrict__ res)
{
    extern __shared__ char gsm[];
    GemmOut go;
    go.C = res;
    go.Cbf = nullptr;
    go.bias = bd;
    go.addend = fromp;
    gemm_core(ch, wd, go, gsm, blockIdx.y * 128, blockIdx.x * 128);
}

// ---------------- scores: bf16, mixing applied in-register ---------------
#define SC_STAGE 30720
#define SC_SMEM  (4 * SC_STAGE + 1024 + 2048 + 2048)

__global__ __launch_bounds__(256) void scores_db_kernel(
    const __nv_bfloat16* __restrict__ qh,
    const __nv_bfloat16* __restrict__ kh,
    const float* __restrict__ mixing,
    const float* __restrict__ cb, __nv_bfloat16* __restrict__ probs,
    float* __restrict__ psum)
{
    extern __shared__ char ssm[];
    float* scb = (float*)(ssm + 4 * SC_STAGE);
    float* sRow = (float*)(ssm + 4 * SC_STAGE + 1024);             // [128][4]
    __nv_bfloat16* smix = (__nv_bfloat16*)(ssm + 4 * SC_STAGE + 1024 + 2048);  // [1024]
    uint32_t smb = smem_u32(ssm);

    int tid = threadIdx.x;
    int lane = tid & 31, wid = tid >> 5;
    int h = blockIdx.z, bm = blockIdx.y * 128, bn = blockIdx.x * 256;
    int wm = (wid & 1) * 64, wn = (wid >> 1) * 64;

    const __nv_bfloat16* Ah = qh + (size_t)bm * DD;
    const __nv_bfloat16* Bh = kh + (size_t)bn * DD;

    scb[tid] = cb[(size_t)(bn + tid) * HH + h];
    {
        int d = tid * 4;
        float4 m = *(const float4*)&mixing[(size_t)h * DD + d];
        *(__nv_bfloat162*)&smix[d]     = __nv_bfloat162(__float2bfloat16(m.x), __float2bfloat16(m.y));
        *(__nv_bfloat162*)&smix[d + 2] = __nv_bfloat162(__float2bfloat16(m.z), __float2bfloat16(m.w));
    }

    float acc[4][8][4];
#pragma unroll
    for (int mi = 0; mi < 4; mi++)
#pragma unroll
        for (int ni = 0; ni < 8; ni++)
#pragma unroll
            for (int j = 0; j < 4; j++) acc[mi][ni][j] = 0.f;

    int ar = tid >> 2, ac = tid & 3;

    auto issue = [&](int c) {
        int s = c & 3;
        int k0 = c * 32;
        uint32_t sb = smb + s * SC_STAGE;
#pragma unroll
        for (int i = 0; i < 2; i++) {
            int row = ar + i * 64;
            cp16(sb + row * 80 + ac * 16, Ah + (size_t)row * DD + k0 + ac * 8);
        }
#pragma unroll
        for (int i = 0; i < 4; i++) {
            int row = ar + i * 64;
            cp16(sb + 10240 + row * 80 + ac * 16, Bh + (size_t)row * DD + k0 + ac * 8);
        }
        CP_COMMIT();
    };

    issue(0); issue(1);

    for (int c = 0; c < 32; c++) {
        if (c + 2 < 32) issue(c + 2);
        if (c < 30) { CP_WAIT2(); } else if (c == 30) { CP_WAIT1(); } else { CP_WAIT0(); }
        __syncthreads();

        const __nv_bfloat16* pAh = (const __nv_bfloat16*)(ssm + (c & 3) * SC_STAGE);
        const __nv_bfloat16* pBh = pAh + 5120;

#pragma unroll
        for (int ks = 0; ks < 2; ks++) {
            int kk = ks * 16 + 2 * (lane & 3);
            int d0 = c * 32 + kk;
            uint32_t m0 = *(const uint32_t*)&smix[d0];
            uint32_t m1 = *(const uint32_t*)&smix[d0 + 8];
            uint32_t ah[4][4];
#pragma unroll
            for (int mi = 0; mi < 4; mi++) {
                int r = wm + mi * 16 + (lane >> 2);
                uint32_t a0 = *(const uint32_t*)&pAh[r * 40 + kk];
                uint32_t a1 = *(const uint32_t*)&pAh[(r + 8) * 40 + kk];
                uint32_t a2 = *(const uint32_t*)&pAh[r * 40 + kk + 8];
                uint32_t a3 = *(const uint32_t*)&pAh[(r + 8) * 40 + kk + 8];
                MULBF2(ah[mi][0], a0, m0);
                MULBF2(ah[mi][1], a1, m0);
                MULBF2(ah[mi][2], a2, m1);
                MULBF2(ah[mi][3], a3, m1);
            }
#pragma unroll
            for (int ni = 0; ni < 8; ni++) {
                int n = wn + ni * 8 + (lane >> 2);
                uint32_t bh0 = *(const uint32_t*)&pBh[n * 40 + kk];
                uint32_t bh1 = *(const uint32_t*)&pBh[n * 40 + kk + 8];
#pragma unroll
                for (int mi = 0; mi < 4; mi++)
                    MMA16816(acc[mi][ni], ah[mi], bh0, bh1);
            }
        }
    }

    // epilogue: exp(logit) -> bf16 probs, per-row partial sums (deterministic)
    __nv_bfloat16* out = probs + ((size_t)h * FF + bm) * TT + bn;
    float rs[4][2];
#pragma unroll
    for (int mi = 0; mi < 4; mi++) { rs[mi][0] = 0.f; rs[mi][1] = 0.f; }
#pragma unroll
    for (int mi = 0; mi < 4; mi++) {
        int frow = wm + mi * 16 + (lane >> 2);
#pragma unroll
        for (int ni = 0; ni < 8; ni++) {
            int tcol = wn + ni * 8 + 2 * (lane & 3);
            float cb0 = scb[tcol], cb1 = scb[tcol + 1];
            float e0 = __expf((acc[mi][ni][0] + cb0) * SCALE);
            float e1 = __expf((acc[mi][ni][1] + cb1) * SCALE);
            float e2 = __expf((acc[mi][ni][2] + cb0) * SCALE);
            float e3 = __expf((acc[mi][ni][3] + cb1) * SCALE);
            rs[mi][0] += e0 + e1;
            rs[mi][1] += e2 + e3;
            __nv_bfloat162 p0 = __nv_bfloat162(__float2bfloat16(e0), __float2bfloat16(e1));
            __nv_bfloat162 p1 = __nv_bfloat162(__float2bfloat16(e2), __float2bfloat16(e3));
            *(__nv_bfloat162*)&out[(size_t)frow * TT + tcol] = p0;
            *(__nv_bfloat162*)&out[(size_t)(frow + 8) * TT + tcol] = p1;
        }
    }
#pragma unroll
    for (int mi = 0; mi < 4; mi++)
#pragma unroll
        for (int rr = 0; rr < 2; rr++) {
            rs[mi][rr] += __shfl_xor_sync(0xffffffffu, rs[mi][rr], 1);
            rs[mi][rr] += __shfl_xor_sync(0xffffffffu, rs[mi][rr], 2);
        }
    int wnidx = wid >> 1;
    __syncthreads();
    if ((lane & 3) == 0) {
#pragma unroll
        for (int mi = 0; mi < 4; mi++) {
            int r0 = wm + mi * 16 + (lane >> 2);
            sRow[r0 * 4 + wnidx] = rs[mi][0];
            sRow[(r0 + 8) * 4 + wnidx] = rs[mi][1];
        }
    }
    __syncthreads();
    if (tid < 128) {
        float s = sRow[tid * 4 + 0] + sRow[tid * 4 + 1]
                + sRow[tid * 4 + 2] + sRow[tid * 4 + 3];
        psum[((size_t)h * FF + bm + tid) * 8 + blockIdx.x] = s;
    }
}

// ---------------- rinv ----------------
__global__ void rinv_kernel(const float* __restrict__ psum, float* __restrict__ rinv) {
    int i = blockIdx.x * 256 + threadIdx.x;
    float s = 0.f;
#pragma unroll
    for (int j = 0; j < 8; j++) s += psum[(size_t)i * 8 + j];
    rinv[i] = 1.0f / s;
}

// ---------------- ctx: bf16 probs @ vT -> bf16, 2-stage, 2 CTAs/SM -------
#define CT_AST 72
#define CT_ASZ (128 * 72 * 2)
#define CT_VSZ (64 * 72 * 2)
#define CT_STAGE (CT_ASZ + CT_VSZ)
#define CT_SMEM (2 * CT_STAGE)

__global__ __launch_bounds__(256, 2) void ctx_db_kernel(
    const __nv_bfloat16* __restrict__ probs, const float* __restrict__ rinv,
    const __nv_bfloat16* __restrict__ vth, __nv_bfloat16* __restrict__ ctxb)
{
    extern __shared__ char csm[];
    uint32_t smb = smem_u32(csm);
    int tid = threadIdx.x;
    int lane = tid & 31, wid = tid >> 5;
    int h = blockIdx.y, bm = blockIdx.x * 128;
    int wm = (wid & 3) * 32, wn = (wid >> 2) * 32;

    const __nv_bfloat16* P = probs + ((size_t)h * FF + bm) * TT;
    const __nv_bfloat16* V = vth + (size_t)h * DH * TT;

    float acc[2][4][4];
#pragma unroll
    for (int mi = 0; mi < 2; mi++)
#pragma unroll
        for (int ni = 0; ni < 4; ni++)
#pragma unroll
            for (int j = 0; j < 4; j++) acc[mi][ni][j] = 0.f;

    int arow = tid >> 3, ac = tid & 7;

    auto issue = [&](int c, int s) {
        int k0 = c * 64;
        uint32_t sb = smb + s * CT_STAGE;
#pragma unroll
        for (int i = 0; i < 4; i++) {
            int row = arow + i * 32;
            cp16(sb + row * 144 + ac * 16, P + (size_t)row * TT + k0 + ac * 8);
        }
#pragma unroll
        for (int i = 0; i < 2; i++) {
            int row = arow + i * 32;
            cp16(sb + CT_ASZ + row * 144 + ac * 16, V + (size_t)row * TT + k0 + ac * 8);
        }
        CP_COMMIT();
    };

    issue(0, 0);

    for (int c = 0; c < 32; c++) {
        int s = c & 1;
        if (c < 31) issue(c + 1, s ^ 1);
        if (c < 31) { CP_WAIT1(); } else { CP_WAIT0(); }
        __syncthreads();

        const __nv_bfloat16* pA = (const __nv_bfloat16*)(csm + s * CT_STAGE);
        const __nv_bfloat16* pV = (const __nv_bfloat16*)(csm + s * CT_STAGE + CT_ASZ);

#pragma unroll
        for (int ks = 0; ks < 4; ks++) {
            int kk = ks * 16 + 2 * (lane & 3);
            uint32_t a[2][4];
#pragma unroll
            for (int mi = 0; mi < 2; mi++) {
                int r = wm + mi * 16 + (lane >> 2);
                a[mi][0] = *(const uint32_t*)&pA[r * CT_AST + kk];
                a[mi][1] = *(const uint32_t*)&pA[(r + 8) * CT_AST + kk];
                a[mi][2] = *(const uint32_t*)&pA[r * CT_AST + kk + 8];
                a[mi][3] = *(const uint32_t*)&pA[(r + 8) * CT_AST + kk + 8];
            }
#pragma unroll
            for (int ni = 0; ni < 4; ni++) {
                int n = wn + ni * 8 + (lane >> 2);
                uint32_t b0 = *(const uint32_t*)&pV[n * CT_AST + kk];
                uint32_t b1 = *(const uint32_t*)&pV[n * CT_AST + kk + 8];
#pragma unroll
                for (int mi = 0; mi < 2; mi++)
                    MMA16816(acc[mi][ni], a[mi], b0, b1);
            }
        }
        __syncthreads();
    }

    const float* rv = rinv + (size_t)h * FF + bm;
    __nv_bfloat16* outp = ctxb + (size_t)bm * DD + h * DH;
#pragma unroll
    for (int mi = 0; mi < 2; mi++) {
        int frow = wm + mi * 16 + (lane >> 2);
        float r0 = rv[frow], r1 = rv[frow + 8];
#pragma unroll
        for (int ni = 0; ni < 4; ni++) {
            int tcol = wn + ni * 8 + 2 * (lane & 3);
            __nv_bfloat162 v0 = __nv_bfloat162(__float2bfloat16(acc[mi][ni][0] * r0),
                                               __float2bfloat16(acc[mi][ni][1] * r0));
            __nv_bfloat162 v1 = __nv_bfloat162(__float2bfloat16(acc[mi][ni][2] * r1),
                                               __float2bfloat16(acc[mi][ni][3] * r1));
            *(__nv_bfloat162*)&outp[(size_t)frow * DD + tcol] = v0;
            *(__nv_bfloat162*)&outp[(size_t)(frow + 8) * DD + tcol] = v1;
        }
    }
}

// ---------------- LayerNorm ----------------
__global__ void ln_kernel(const float* __restrict__ res,
                          const float* __restrict__ gamma,
                          const float* __restrict__ beta,
                          float* __restrict__ out) {
    int r = blockIdx.x;
    const float* row = res + (size_t)r * DD;
    float* orow = out + (size_t)r * DD;
    __shared__ float red[256];
    int tid = threadIdx.x;
    float4 x = *(const float4*)&row[tid * 4];
    float s = x.x + x.y + x.z + x.w;
    red[tid] = s;
    __syncthreads();
    for (int st = 128; st; st >>= 1) {
        if (tid < st) red[tid] += red[tid + st];
        __syncthreads();
    }
    float mean = red[0] * (1.0f / DD);
    __syncthreads();
    float dx = x.x - mean, dy = x.y - mean, dz = x.z - mean, dw = x.w - mean;
    red[tid] = dx * dx + dy * dy + dz * dz + dw * dw;
    __syncthreads();
    for (int st = 128; st; st >>= 1) {
        if (tid < st) red[tid] += red[tid + st];
        __syncthreads();
    }
    float var = red[0] * (1.0f / DD);
    float rstd = rsqrtf(var + kLnEps);
    float4 g = *(const float4*)&gamma[tid * 4];
    float4 b = *(const float4*)&beta[tid * 4];
    float4 o;
    o.x = dx * rstd * g.x + b.x;
    o.y = dy * rstd * g.y + b.y;
    o.z = dz * rstd * g.z + b.z;
    o.w = dw * rstd * g.w + b.w;
    *(float4*)&orow[tid * 4] = o;
}

// ---------------- launch ----------------
extern "C" void kernel_launch(void* const* d_in, const int* in_sizes, int n_in,
                              void* d_out, int out_size) {
    const float* hidden = (const float*)d_in[0];
    const int* fpos = (const int*)d_in[1];
    const int* tpos = (const int*)d_in[2];
    const float* Wq = (const float*)d_in[3];
    const float* Wk = (const float*)d_in[4];
    const float* Wcb = (const float*)d_in[5];
    const float* Wv = (const float*)d_in[6];
    const float* bv = (const float*)d_in[7];
    const float* mixing = (const float*)d_in[8];
    const float* Wd = (const float*)d_in[9];
    const float* bd = (const float*)d_in[10];
    const float* gamma = (const float*)d_in[11];
    const float* beta = (const float*)d_in[12];
    float* out = (float*)d_out;

    float *p_from, *p_to, *p_v, *p_cb, *p_scores, *p_res;
    float *p_psum, *p_rinv;
    __nv_bfloat16 *p_qh, *p_kh;
    __nv_bfloat16 *p_fh, *p_th, *p_ch;
    __nv_bfloat16 *p_wqh, *p_wkh, *p_wvh, *p_wdh, *p_vth;
    cudaGetSymbolAddress((void**)&p_from, g_from);
    cudaGetSymbolAddress((void**)&p_to, g_to);
    cudaGetSymbolAddress((void**)&p_v, g_v);
    cudaGetSymbolAddress((void**)&p_cb, g_cb);
    cudaGetSymbolAddress((void**)&p_scores, g_scores);
    cudaGetSymbolAddress((void**)&p_res, g_res);
    cudaGetSymbolAddress((void**)&p_psum, g_psum);
    cudaGetSymbolAddress((void**)&p_rinv, g_rinv);
    cudaGetSymbolAddress((void**)&p_qh, g_qh);
    cudaGetSymbolAddress((void**)&p_kh, g_kh);
    cudaGetSymbolAddress((void**)&p_fh, g_fh);
    cudaGetSymbolAddress((void**)&p_th, g_th);
    cudaGetSymbolAddress((void**)&p_ch, g_ch);
    cudaGetSymbolAddress((void**)&p_wqh, g_wqh);
    cudaGetSymbolAddress((void**)&p_wkh, g_wkh);
    cudaGetSymbolAddress((void**)&p_wvh, g_wvh);
    cudaGetSymbolAddress((void**)&p_wdh, g_wdh);
    cudaGetSymbolAddress((void**)&p_vth, g_vth);

    __nv_bfloat16* p_probs = (__nv_bfloat16*)p_scores;

    cudaFuncSetAttribute(scores_db_kernel,
                         cudaFuncAttributeMaxDynamicSharedMemorySize, SC_SMEM);
    cudaFuncSetAttribute(qkv_kernel,
                         cudaFuncAttributeMaxDynamicSharedMemorySize, GM_SMEM);
    cudaFuncSetAttribute(outgemm_kernel,
                         cudaFuncAttributeMaxDynamicSharedMemorySize, GM_SMEM);
    cudaFuncSetAttribute(ctx_db_kernel,
                         cudaFuncAttributeMaxDynamicSharedMemorySize, CT_SMEM);
    cudaFuncSetAttribute(cb_kernel,
                         cudaFuncAttributeMaxDynamicSharedMemorySize, CB_SMEM);

    dim3 tb(32, 8);

    gather_kernel<<<FF, 256>>>(hidden, fpos, tpos);
    transpose_w4_kernel<<<dim3(DD / 32, DD / 32, 4), tb>>>(
        Wq, Wk, Wv, Wd, p_wqh, p_wkh, p_wvh, p_wdh);

    qkv_kernel<<<dim3(DD / 128, FF / 128, 3), 256, GM_SMEM>>>(
        p_fh, p_th, p_wqh, p_wkh, p_wvh, bv, p_qh, p_kh, p_v);
    cb_kernel<<<TT / 8, 256, CB_SMEM>>>(Wcb, p_cb);

    transpose_h_kernel<<<dim3(DD / 32, TT / 32), tb>>>(p_v, TT, DD, p_vth);

    scores_db_kernel<<<dim3(TT / 256, FF / 128, HH), 256, SC_SMEM>>>(
        p_qh, p_kh, mixing, p_cb, p_probs, p_psum);

    rinv_kernel<<<HH * FF / 256, 256>>>(p_psum, p_rinv);
    ctx_db_kernel<<<dim3(FF / 128, HH), 256, CT_SMEM>>>(p_probs, p_rinv, p_vth, p_ch);

    outgemm_kernel<<<dim3(DD / 128, FF / 128), 256, GM_SMEM>>>(
        p_ch, p_wdh, bd, p_from, p_res);
    ln_kernel<<<FF, 256>>>(p_res, gamma, beta, out);
    (void)in_sizes; (void)n_in; (void)out_size;
}